// round 14
// baseline (speedup 1.0000x reference)
#include <cuda_runtime.h>
#include <cuda_fp16.h>
#include <cstdint>

#define BB 4
#define CC 256
#define NN 4096
#define DD 32
#define KT 64
#define NKT (NN / KT)

// Scratch: pre-split half precision operands
__device__ __half g_qh[BB * NN * DD];
__device__ __half g_ql[BB * NN * DD];
__device__ __half g_kh[BB * NN * DD];
__device__ __half g_kl[BB * NN * DD];   // still produced; unused by attn now
__device__ __half g_vh[BB * CC * NN];   // [B][C][N]

// ---------------------------------------------------------------------------
__device__ __forceinline__ void mma16(float* d, const uint32_t* a,
                                      uint32_t b0, uint32_t b1) {
    asm("mma.sync.aligned.m16n8k16.row.col.f32.f16.f16.f32 "
        "{%0,%1,%2,%3},{%4,%5,%6,%7},{%8,%9},{%0,%1,%2,%3};"
        : "+f"(d[0]), "+f"(d[1]), "+f"(d[2]), "+f"(d[3])
        : "r"(a[0]), "r"(a[1]), "r"(a[2]), "r"(a[3]), "r"(b0), "r"(b1));
}
#define LDSM4(r, addr) \
    asm volatile("ldmatrix.sync.aligned.m8n8.x4.shared.b16 {%0,%1,%2,%3}, [%4];" \
        : "=r"((r)[0]), "=r"((r)[1]), "=r"((r)[2]), "=r"((r)[3]) : "r"(addr))

__device__ __forceinline__ uint32_t s2u(const void* p) {
    uint32_t a;
    asm("{ .reg .u64 t; cvta.to.shared.u64 t, %1; cvt.u32.u64 %0, t; }"
        : "=r"(a) : "l"(p));
    return a;
}
__device__ __forceinline__ void cp16(uint32_t dst, const void* src) {
    asm volatile("cp.async.cg.shared.global [%0], [%1], 16;"
                 :: "r"(dst), "l"(src) : "memory");
}
__device__ __forceinline__ void cp_commit() {
    asm volatile("cp.async.commit_group;" ::: "memory");
}
__device__ __forceinline__ void cp_wait0() {
    asm volatile("cp.async.wait_group 0;" ::: "memory");
}
__device__ __forceinline__ uint32_t pk2(float a, float b) {
    __half2 h = __floats2half2_rn(a, b);
    return *(uint32_t*)&h;
}
__device__ __forceinline__ uint32_t pk2h(__half a, __half b) {
    __half2 h = __halves2half2(a, b);
    return *(uint32_t*)&h;
}

// ===========================================================================
// Fused projections (UNCHANGED from R10). grid = 512 x 256 thr, occ 2.
// ===========================================================================
#define PF_INH 0
#define PF_INL 4352
#define PF_WH  8704
#define PF_WL_QK 12928
#define PF_WL_V  13312
#define PF_TOT 17920

__global__ void __launch_bounds__(256, 2)
proj_fused(const float* __restrict__ sem, const float* __restrict__ str,
           const float* __restrict__ Wq, const float* __restrict__ bq,
           const float* __restrict__ Wk, const float* __restrict__ bk,
           const float* __restrict__ Wv, const float* __restrict__ bv)
{
    extern __shared__ uint32_t smp[];
    uint32_t* INH = smp + PF_INH;
    uint32_t* INL = smp + PF_INL;
    uint32_t* WH  = smp + PF_WH;

    const int t    = threadIdx.x;
    const int lane = t & 31;
    const int wid  = t >> 5;
    const int lq   = lane >> 2;
    const int lr   = lane & 3;
    const int bx   = blockIdx.x;

    if (bx < 256) {
        uint32_t* WL = smp + PF_WL_V;
        const int b   = bx >> 6;
        const int px0 = ((bx >> 1) & 31) << 7;
        const int cb  = (bx & 1) << 7;
        const int r0  = wid * 16;

        float cv[16][4];
        #pragma unroll
        for (int n = 0; n < 16; ++n)
            #pragma unroll
            for (int k = 0; k < 4; ++k) cv[n][k] = 0.f;

        for (int chunk = 0; chunk < 4; ++chunk) {
            if (chunk) __syncthreads();
            #pragma unroll
            for (int it = 0; it < 16; ++it) {
                int idx = it * 256 + t;
                int i = idx >> 7, px = idx & 127;
                size_t g = (size_t)(b * CC + chunk * 64 + 2 * i) * NN + px0 + px;
                float x0 = str[g], x1 = str[g + NN];
                __half h0 = __float2half_rn(x0), h1 = __float2half_rn(x1);
                INH[i * 136 + px] = pk2h(h0, h1);
                INL[i * 136 + px] = pk2(x0 - __half2float(h0), x1 - __half2float(h1));
            }
            #pragma unroll
            for (int it = 0; it < 16; ++it) {
                int idx = it * 256 + t;
                int cc = idx >> 5, pr = idx & 31;
                float2 w = *(const float2*)&Wv[(size_t)(cb + cc) * CC + chunk * 64 + 2 * pr];
                __half h0 = __float2half_rn(w.x), h1 = __float2half_rn(w.y);
                WH[cc * 36 + pr] = pk2h(h0, h1);
                WL[cc * 36 + pr] = pk2(w.x - __half2float(h0), w.y - __half2float(h1));
            }
            __syncthreads();

            #pragma unroll
            for (int s = 0; s < 4; ++s) {
                uint32_t ah[4], al[4];
                ah[0] = WH[(r0 + lq) * 36 + 8 * s + lr];
                ah[1] = WH[(r0 + lq + 8) * 36 + 8 * s + lr];
                ah[2] = WH[(r0 + lq) * 36 + 8 * s + lr + 4];
                ah[3] = WH[(r0 + lq + 8) * 36 + 8 * s + lr + 4];
                al[0] = WL[(r0 + lq) * 36 + 8 * s + lr];
                al[1] = WL[(r0 + lq + 8) * 36 + 8 * s + lr];
                al[2] = WL[(r0 + lq) * 36 + 8 * s + lr + 4];
                al[3] = WL[(r0 + lq + 8) * 36 + 8 * s + lr + 4];
                const int ro  = (8 * s + lr) * 136;
                const int ro4 = (8 * s + lr + 4) * 136;
                #pragma unroll
                for (int n = 0; n < 16; ++n) {
                    uint32_t bh0 = INH[ro + 8 * n + lq];
                    uint32_t bh1 = INH[ro4 + 8 * n + lq];
                    uint32_t bl0 = INL[ro + 8 * n + lq];
                    uint32_t bl1 = INL[ro4 + 8 * n + lq];
                    mma16(cv[n], ah, bh0, bh1);
                    mma16(cv[n], al, bh0, bh1);
                    mma16(cv[n], ah, bl0, bl1);
                }
            }
        }

        uint32_t* ov = (uint32_t*)g_vh;
        const int ccr = cb + r0 + lq;
        float b0 = __ldg(&bv[ccr]), b8 = __ldg(&bv[ccr + 8]);
        size_t o0 = ((size_t)(b * CC + ccr) * NN + px0) >> 1;
        size_t o8 = o0 + 8 * (NN / 2);
        #pragma unroll
        for (int n = 0; n < 16; ++n) {
            ov[o0 + 4 * n + lr] = pk2(cv[n][0] + b0, cv[n][1] + b0);
            ov[o8 + 4 * n + lr] = pk2(cv[n][2] + b8, cv[n][3] + b8);
        }
    } else {
        uint32_t* WL = smp + PF_WL_QK;
        const int sub  = bx - 256;
        const int pass = sub >> 7;
        const int sidx = sub & 127;
        const int b    = sidx >> 5;
        const int px0  = (sidx & 31) << 7;
        const int wm   = wid & 3;
        const int wn   = wid >> 2;

        const float* inp = pass ? str : sem;
        const float* Wp  = pass ? Wk  : Wq;
        const float* bp  = pass ? bk  : bq;
        uint32_t* oh = (uint32_t*)(pass ? g_kh : g_qh);
        uint32_t* ol = (uint32_t*)(pass ? g_kl : g_ql);

        #pragma unroll
        for (int it = 0; it < 16; ++it) {
            int idx = it * 256 + t;
            int d = idx >> 7, pr = idx & 127;
            float2 w = *(const float2*)&Wp[d * CC + 2 * pr];
            __half h0 = __float2half_rn(w.x), h1 = __float2half_rn(w.y);
            WH[d * 132 + pr] = pk2h(h0, h1);
            WL[d * 132 + pr] = pk2(w.x - __half2float(h0), w.y - __half2float(h1));
        }

        float cq[2][2][4];
        #pragma unroll
        for (int mm = 0; mm < 2; ++mm)
            #pragma unroll
            for (int n = 0; n < 2; ++n)
                #pragma unroll
                for (int k = 0; k < 4; ++k) cq[mm][n][k] = 0.f;

        for (int chunk = 0; chunk < 4; ++chunk) {
            __syncthreads();
            #pragma unroll
            for (int it = 0; it < 16; ++it) {
                int idx = it * 256 + t;
                int i = idx >> 7, px = idx & 127;
                size_t g = (size_t)(b * CC + chunk * 64 + 2 * i) * NN + px0 + px;
                float x0 = inp[g], x1 = inp[g + NN];
                __half h0 = __float2half_rn(x0), h1 = __float2half_rn(x1);
                INH[i * 136 + px] = pk2h(h0, h1);
                INL[i * 136 + px] = pk2(x0 - __half2float(h0), x1 - __half2float(h1));
            }
            __syncthreads();

            #pragma unroll
            for (int s = 0; s < 4; ++s) {
                uint32_t ah[2][4], al[2][4];
                const int ro  = (8 * s + lr) * 136;
                const int ro4 = (8 * s + lr + 4) * 136;
                #pragma unroll
                for (int mm = 0; mm < 2; ++mm) {
                    int pxm = wm * 32 + mm * 16 + lq;
                    ah[mm][0] = INH[ro + pxm];  ah[mm][1] = INH[ro + pxm + 8];
                    ah[mm][2] = INH[ro4 + pxm]; ah[mm][3] = INH[ro4 + pxm + 8];
                    al[mm][0] = INL[ro + pxm];  al[mm][1] = INL[ro + pxm + 8];
                    al[mm][2] = INL[ro4 + pxm]; al[mm][3] = INL[ro4 + pxm + 8];
                }
                #pragma unroll
                for (int n = 0; n < 2; ++n) {
                    int drow = ((wn * 2 + n) * 8 + lq) * 132 + chunk * 32;
                    uint32_t bh0 = WH[drow + 8 * s + lr];
                    uint32_t bh1 = WH[drow + 8 * s + lr + 4];
                    uint32_t bl0 = WL[drow + 8 * s + lr];
                    uint32_t bl1 = WL[drow + 8 * s + lr + 4];
                    #pragma unroll
                    for (int mm = 0; mm < 2; ++mm) {
                        mma16(cq[mm][n], ah[mm], bh0, bh1);
                        mma16(cq[mm][n], al[mm], bh0, bh1);
                        mma16(cq[mm][n], ah[mm], bl0, bl1);
                    }
                }
            }
        }

        #pragma unroll
        for (int mm = 0; mm < 2; ++mm) {
            #pragma unroll
            for (int n = 0; n < 2; ++n) {
                int pxr = px0 + wm * 32 + mm * 16 + lq;
                int d0  = (wn * 2 + n) * 8 + 2 * lr;
                float b0 = __ldg(&bp[d0]), b1 = __ldg(&bp[d0 + 1]);
                float q0 = cq[mm][n][0] + b0, q1 = cq[mm][n][1] + b1;
                float q2 = cq[mm][n][2] + b0, q3 = cq[mm][n][3] + b1;
                __half h0 = __float2half_rn(q0), h1 = __float2half_rn(q1);
                __half h2 = __float2half_rn(q2), h3 = __float2half_rn(q3);
                size_t i0w = (size_t)(b * NN + pxr) * 16 + (wn * 2 + n) * 4 + lr;
                oh[i0w]       = pk2h(h0, h1);
                ol[i0w]       = pk2(q0 - __half2float(h0), q1 - __half2float(h1));
                oh[i0w + 128] = pk2h(h2, h3);
                ol[i0w + 128] = pk2(q2 - __half2float(h2), q3 - __half2float(h3));
            }
        }
    }
}

// ---------------------------------------------------------------------------
// A: fp16 mma flash attention, 2-term S (qh·kh + ql·kh), Q-hi pinned in regs,
// ldmatrix + one-tile-deferred PV pipeline. 512 thr, grid = 128.
// ---------------------------------------------------------------------------
#define SQH 0
#define SQL 10240
#define SKB 20480       // 2 x 5120 (K hi only)
#define SVB 30720       // 2 x 36864
#define SPS 104448      // 2 x 16384
#define PBUF 16384
#define SLS 137216
#define SM_AT 139264

__device__ __forceinline__ void load_k_tile(uint32_t smb, const __half* kh,
                                            int j0, int buf, int t)
{
    if (t < 256) {
        int row = t >> 2, seg = t & 3;
        cp16(smb + SKB + buf * 5120 + row * 80 + seg * 16,
             kh + (size_t)(j0 + row) * DD + seg * 8);
    }
}
__device__ __forceinline__ void load_v_tile(uint32_t smb, const __half* vh,
                                            int j0, int buf, int t)
{
    #pragma unroll
    for (int i = 0; i < 4; ++i) {
        int idx = i * 512 + t;
        int c = idx >> 3, seg = idx & 7;
        cp16(smb + SVB + buf * 36864 + c * 144 + seg * 16,
             vh + (size_t)c * NN + j0 + seg * 8);
    }
}

__global__ void __launch_bounds__(512, 1)
attn_mma_kernel(const float* __restrict__ sem, const float* __restrict__ gammaP,
                float* __restrict__ out)
{
    extern __shared__ char smc[];
    const uint32_t smb = s2u(smc);
    float* red = (float*)(smc + SLS);

    const int t    = threadIdx.x;
    const int lane = t & 31;
    const int wid  = t >> 5;
    const int wm   = wid & 3;
    const int wn   = wid >> 2;
    const int R0   = wm * 32;
    const int J0   = wn * 16;
    const int C0w  = wn * 64;
    const int lq   = lane >> 2;
    const int lr   = lane & 3;
    const int l8   = lane & 7;
    const int gp   = lane >> 3;

    const int b  = blockIdx.x >> 5;
    const int i0 = (blockIdx.x & 31) << 7;

    const __half* khb = g_kh + (size_t)b * NN * DD;
    const __half* vhb = g_vh + (size_t)b * CC * NN;

    // preload Q (hi+lo) and K tile 0
    #pragma unroll
    for (int i = 0; i < 2; ++i) {
        int idx = i * 512 + t;
        int row = (idx >> 2) & 127, seg = idx & 3;
        const __half* src = (idx < 512 ? g_qh : g_ql) +
                            ((size_t)(b * NN + i0 + row)) * DD + seg * 8;
        cp16(smb + (idx < 512 ? SQH : SQL) + row * 80 + seg * 16, src);
    }
    load_k_tile(smb, khb, 0, 0, t);
    cp_commit();
    cp_wait0();
    __syncthreads();

    // ---- pin Q-hi fragments in registers (constant across all tiles) ----
    uint32_t qhr[2][2][4];
    uint32_t qladr[2][2];
    #pragma unroll
    for (int s = 0; s < 2; ++s)
        #pragma unroll
        for (int m = 0; m < 2; ++m) {
            int qrow = R0 + 16 * m + l8 + ((gp & 1) << 3);
            int qcol = 16 * s + ((gp & 2) << 2);
            uint32_t qa = smb + SQH + (qrow * 40 + qcol) * 2;
            LDSM4(qhr[s][m], qa);
            qladr[s][m] = qa + (SQL - SQH);
        }

    // hoisted P-store offsets: row part for (m) and chunk part for (n)
    // store addr = psw + pst_m[m] + ((h ^ lq) << 4)   where h = wn*2+n
    uint32_t pst_m[2];
    #pragma unroll
    for (int m = 0; m < 2; ++m)
        pst_m[m] = (uint32_t)((R0 + 16 * m + lq) * 128 + lr * 4);
    // hoisted P-read row offsets
    uint32_t prd_m[2];
    #pragma unroll
    for (int m = 0; m < 2; ++m)
        prd_m[m] = (uint32_t)((R0 + 16 * m + l8 + ((gp & 1) << 3)) * 128);
    const int pgb = (gp & 2) >> 1;

    float oacc[2][8][4];
    #pragma unroll
    for (int m = 0; m < 2; ++m)
        #pragma unroll
        for (int n = 0; n < 8; ++n)
            #pragma unroll
            for (int k = 0; k < 4; ++k) oacc[m][n][k] = 0.f;
    float lsum[4] = {0.f, 0.f, 0.f, 0.f};
    float mrun[4] = {-1e30f, -1e30f, -1e30f, -1e30f};
    float fp[4]   = {1.f, 1.f, 1.f, 1.f};

    for (int kt = 0; kt < NKT; ++kt) {
        const int kbuf = kt & 1;
        const uint32_t psw = smb + SPS + kbuf * PBUF;
        const uint32_t psr = smb + SPS + (kbuf ^ 1) * PBUF;
        const uint32_t vbase = smb + SVB + (kbuf ^ 1) * 36864;

        if (kt + 1 < NKT)
            load_k_tile(smb, khb, (kt + 1) * KT, kbuf ^ 1, t);
        load_v_tile(smb, vhb, kt * KT, kbuf, t);
        cp_commit();

        // ---- S = Q K^T (2-term: qh·kh + ql·kh) ----
        const uint32_t kbase = smb + SKB + kbuf * 5120;
        float sacc[2][2][4];
        #pragma unroll
        for (int m = 0; m < 2; ++m)
            #pragma unroll
            for (int n = 0; n < 2; ++n)
                #pragma unroll
                for (int k = 0; k < 4; ++k) sacc[m][n][k] = 0.f;

        #pragma unroll
        for (int s = 0; s < 2; ++s) {
            uint32_t ql[2][4];
            LDSM4(ql[0], qladr[s][0]);
            LDSM4(ql[1], qladr[s][1]);
            int krow = J0 + l8 + ((gp & 2) << 2);
            int kcol = 16 * s + ((gp & 1) << 3);
            uint32_t kh[4];
            LDSM4(kh, kbase + (krow * 40 + kcol) * 2);
            #pragma unroll
            for (int n = 0; n < 2; ++n) {
                #pragma unroll
                for (int m = 0; m < 2; ++m) {
                    mma16(sacc[m][n], qhr[s][m], kh[2 * n], kh[2 * n + 1]);
                    mma16(sacc[m][n], ql[m],     kh[2 * n], kh[2 * n + 1]);
                }
            }
        }

        // ---- per-tile max partials ----
        float smax[4];
        #pragma unroll
        for (int m = 0; m < 2; ++m) {
            smax[2 * m] = fmaxf(fmaxf(sacc[m][0][0], sacc[m][0][1]),
                                fmaxf(sacc[m][1][0], sacc[m][1][1]));
            smax[2 * m + 1] = fmaxf(fmaxf(sacc[m][0][2], sacc[m][0][3]),
                                    fmaxf(sacc[m][1][2], sacc[m][1][3]));
        }
        #pragma unroll
        for (int i = 0; i < 4; ++i) {
            smax[i] = fmaxf(smax[i], __shfl_xor_sync(0xFFFFFFFFu, smax[i], 1));
            smax[i] = fmaxf(smax[i], __shfl_xor_sync(0xFFFFFFFFu, smax[i], 2));
        }
        if (lr == 0) {
            #pragma unroll
            for (int i = 0; i < 4; ++i)
                red[wn * 128 + R0 + 8 * i + lq] = smax[i];
        }
        __syncthreads();   // sync A

        // ---- deferred oacc rescale by f(kt-1) ----
        if (kt > 0 && (fp[0] < 1.f || fp[1] < 1.f || fp[2] < 1.f || fp[3] < 1.f)) {
            #pragma unroll
            for (int m = 0; m < 2; ++m)
                #pragma unroll
                for (int n = 0; n < 8; ++n) {
                    oacc[m][n][0] *= fp[2 * m];
                    oacc[m][n][1] *= fp[2 * m];
                    oacc[m][n][2] *= fp[2 * m + 1];
                    oacc[m][n][3] *= fp[2 * m + 1];
                }
        }

        // ---- new running max + f(kt) ----
        float f[4];
        #pragma unroll
        for (int i = 0; i < 4; ++i) {
            int r = R0 + 8 * i + lq;
            float mt = fmaxf(fmaxf(red[r], red[128 + r]),
                             fmaxf(red[256 + r], red[384 + r]));
            float mn = fmaxf(mrun[i], mt);
            f[i] = __expf(mrun[i] - mn);
            mrun[i] = mn;
            lsum[i] *= f[i];
        }

        // ---- interleaved: PV(kt-1) chunks + exp/store P(kt) blocks ----
        #pragma unroll
        for (int kk = 0; kk < 4; ++kk) {
            uint32_t pa[2][4];
            if (kt > 0) {
                int pch = 2 * kk + pgb;
                uint32_t pofs = (uint32_t)((pch ^ l8) << 4);
                LDSM4(pa[0], psr + prd_m[0] + pofs);
                LDSM4(pa[1], psr + prd_m[1] + pofs);
            }
            {   // exp block kk: m = kk>>1, n = kk&1
                const int m = kk >> 1, n = kk & 1;
                int h = wn * 2 + n;
                float p0 = __expf(sacc[m][n][0] - mrun[2 * m]);
                float p1 = __expf(sacc[m][n][1] - mrun[2 * m]);
                float p2 = __expf(sacc[m][n][2] - mrun[2 * m + 1]);
                float p3 = __expf(sacc[m][n][3] - mrun[2 * m + 1]);
                lsum[2 * m]     += p0 + p1;
                lsum[2 * m + 1] += p2 + p3;
                uint32_t a0 = psw + pst_m[m] + ((h ^ lq) << 4);
                asm volatile("st.shared.b32 [%0], %1;" :: "r"(a0), "r"(pk2(p0, p1)) : "memory");
                asm volatile("st.shared.b32 [%0], %1;" :: "r"(a0 + 1024), "r"(pk2(p2, p3)) : "memory");
            }
            if (kt > 0) {
                #pragma unroll
                for (int np = 0; np < 4; ++np) {
                    int vrow = C0w + 16 * np + l8 + ((gp & 2) << 2);
                    int vcol = 16 * kk + ((gp & 1) << 3);
                    uint32_t va = vbase + (vrow * 72 + vcol) * 2;
                    uint32_t vv[4];
                    LDSM4(vv, va);
                    mma16(oacc[0][2 * np],     pa[0], vv[0], vv[1]);
                    mma16(oacc[0][2 * np + 1], pa[0], vv[2], vv[3]);
                    mma16(oacc[1][2 * np],     pa[1], vv[0], vv[1]);
                    mma16(oacc[1][2 * np + 1], pa[1], vv[2], vv[3]);
                }
            }
        }
        #pragma unroll
        for (int i = 0; i < 4; ++i) fp[i] = f[i];

        cp_wait0();
        __syncthreads();   // sync B
    }

    // ---- drain: PV(NKT-1) ----
    {
        const uint32_t psr = smb + SPS + ((NKT - 1) & 1) * PBUF;
        const uint32_t vbase = smb + SVB + ((NKT - 1) & 1) * 36864;
        if (fp[0] < 1.f || fp[1] < 1.f || fp[2] < 1.f || fp[3] < 1.f) {
            #pragma unroll
            for (int m = 0; m < 2; ++m)
                #pragma unroll
                for (int n = 0; n < 8; ++n) {
                    oacc[m][n][0] *= fp[2 * m];
                    oacc[m][n][1] *= fp[2 * m];
                    oacc[m][n][2] *= fp[2 * m + 1];
                    oacc[m][n][3] *= fp[2 * m + 1];
                }
        }
        #pragma unroll
        for (int kk = 0; kk < 4; ++kk) {
            uint32_t pa[2][4];
            int pch = 2 * kk + pgb;
            uint32_t pofs = (uint32_t)((pch ^ l8) << 4);
            LDSM4(pa[0], psr + prd_m[0] + pofs);
            LDSM4(pa[1], psr + prd_m[1] + pofs);
            #pragma unroll
            for (int np = 0; np < 4; ++np) {
                int vrow = C0w + 16 * np + l8 + ((gp & 2) << 2);
                int vcol = 16 * kk + ((gp & 1) << 3);
                uint32_t va = vbase + (vrow * 72 + vcol) * 2;
                uint32_t vv[4];
                LDSM4(vv, va);
                mma16(oacc[0][2 * np],     pa[0], vv[0], vv[1]);
                mma16(oacc[0][2 * np + 1], pa[0], vv[2], vv[3]);
                mma16(oacc[1][2 * np],     pa[1], vv[0], vv[1]);
                mma16(oacc[1][2 * np + 1], pa[1], vv[2], vv[3]);
            }
        }
    }

    // ---- l reduction ----
    #pragma unroll
    for (int i = 0; i < 4; ++i) {
        lsum[i] += __shfl_xor_sync(0xFFFFFFFFu, lsum[i], 1);
        lsum[i] += __shfl_xor_sync(0xFFFFFFFFu, lsum[i], 2);
    }
    __syncthreads();
    if (lr == 0) {
        #pragma unroll
        for (int i = 0; i < 4; ++i)
            red[wn * 128 + R0 + 8 * i + lq] = lsum[i];
    }
    __syncthreads();

    float linv[4];
    #pragma unroll
    for (int i = 0; i < 4; ++i) {
        int r = R0 + 8 * i + lq;
        linv[i] = 1.f / (red[r] + red[128 + r] + red[256 + r] + red[384 + r]);
    }

    // ---- epilogue ----
    const float g = gammaP[0];
    #pragma unroll
    for (int m = 0; m < 2; ++m) {
        #pragma unroll
        for (int n = 0; n < 8; ++n) {
            int ch = C0w + 8 * n + 2 * lr;
            size_t ia = ((size_t)(b * CC + ch)) * NN + i0 + R0 + 16 * m + lq;
            out[ia]          = g * oacc[m][n][0] * linv[2 * m]     + sem[ia];
            out[ia + NN]     = g * oacc[m][n][1] * linv[2 * m]     + sem[ia + NN];
            out[ia + 8]      = g * oacc[m][n][2] * linv[2 * m + 1] + sem[ia + 8];
            out[ia + NN + 8] = g * oacc[m][n][3] * linv[2 * m + 1] + sem[ia + NN + 8];
        }
    }
}

// ---------------------------------------------------------------------------
extern "C" void kernel_launch(void* const* d_in, const int* in_sizes, int n_in,
                              void* d_out, int out_size)
{
    const float* sem = (const float*)d_in[0];
    const float* str = (const float*)d_in[1];
    const float* Wq  = (const float*)d_in[2];
    const float* bq  = (const float*)d_in[3];
    const float* Wk  = (const float*)d_in[4];
    const float* bk  = (const float*)d_in[5];
    const float* Wv  = (const float*)d_in[6];
    const float* bv  = (const float*)d_in[7];
    const float* gam = (const float*)d_in[8];
    float* out = (float*)d_out;

    const int smem_pf = PF_TOT * 4;
    const int smem_at = SM_AT;

    cudaFuncSetAttribute(proj_fused,
        cudaFuncAttributeMaxDynamicSharedMemorySize, smem_pf);
    cudaFuncSetAttribute(attn_mma_kernel,
        cudaFuncAttributeMaxDynamicSharedMemorySize, smem_at);

    proj_fused<<<512, 256, smem_pf>>>(sem, str, Wq, bq, Wk, bk, Wv, bv);
    attn_mma_kernel<<<BB * (NN / 128), 512, smem_at>>>(sem, gam, out);
}

// round 15
// speedup vs baseline: 1.1104x; 1.1104x over previous
#include <cuda_runtime.h>
#include <cuda_fp16.h>
#include <cstdint>

#define BB 4
#define CC 256
#define NN 4096
#define DD 32
#define KT2 128
#define NT2 (NN / KT2)   // 32 big tiles

// Scratch: pre-split half precision operands
__device__ __half g_qh[BB * NN * DD];
__device__ __half g_ql[BB * NN * DD];
__device__ __half g_kh[BB * NN * DD];
__device__ __half g_kl[BB * NN * DD];   // produced by proj; unused by attn
__device__ __half g_vh[BB * CC * NN];   // [B][C][N]

// ---------------------------------------------------------------------------
__device__ __forceinline__ void mma16(float* d, const uint32_t* a,
                                      uint32_t b0, uint32_t b1) {
    asm("mma.sync.aligned.m16n8k16.row.col.f32.f16.f16.f32 "
        "{%0,%1,%2,%3},{%4,%5,%6,%7},{%8,%9},{%0,%1,%2,%3};"
        : "+f"(d[0]), "+f"(d[1]), "+f"(d[2]), "+f"(d[3])
        : "r"(a[0]), "r"(a[1]), "r"(a[2]), "r"(a[3]), "r"(b0), "r"(b1));
}
#define LDSM4(r, addr) \
    asm volatile("ldmatrix.sync.aligned.m8n8.x4.shared.b16 {%0,%1,%2,%3}, [%4];" \
        : "=r"((r)[0]), "=r"((r)[1]), "=r"((r)[2]), "=r"((r)[3]) : "r"(addr))

__device__ __forceinline__ uint32_t s2u(const void* p) {
    uint32_t a;
    asm("{ .reg .u64 t; cvta.to.shared.u64 t, %1; cvt.u32.u64 %0, t; }"
        : "=r"(a) : "l"(p));
    return a;
}
__device__ __forceinline__ void cp16(uint32_t dst, const void* src) {
    asm volatile("cp.async.cg.shared.global [%0], [%1], 16;"
                 :: "r"(dst), "l"(src) : "memory");
}
__device__ __forceinline__ void cp_commit() {
    asm volatile("cp.async.commit_group;" ::: "memory");
}
__device__ __forceinline__ void cp_wait0() {
    asm volatile("cp.async.wait_group 0;" ::: "memory");
}
__device__ __forceinline__ uint32_t pk2(float a, float b) {
    __half2 h = __floats2half2_rn(a, b);
    return *(uint32_t*)&h;
}
__device__ __forceinline__ uint32_t pk2h(__half a, __half b) {
    __half2 h = __halves2half2(a, b);
    return *(uint32_t*)&h;
}

// ===========================================================================
// Fused projections (UNCHANGED from R10). grid = 512 x 256 thr, occ 2.
// ===========================================================================
#define PF_INH 0
#define PF_INL 4352
#define PF_WH  8704
#define PF_WL_QK 12928
#define PF_WL_V  13312
#define PF_TOT 17920

__global__ void __launch_bounds__(256, 2)
proj_fused(const float* __restrict__ sem, const float* __restrict__ str,
           const float* __restrict__ Wq, const float* __restrict__ bq,
           const float* __restrict__ Wk, const float* __restrict__ bk,
           const float* __restrict__ Wv, const float* __restrict__ bv)
{
    extern __shared__ uint32_t smp[];
    uint32_t* INH = smp + PF_INH;
    uint32_t* INL = smp + PF_INL;
    uint32_t* WH  = smp + PF_WH;

    const int t    = threadIdx.x;
    const int lane = t & 31;
    const int wid  = t >> 5;
    const int lq   = lane >> 2;
    const int lr   = lane & 3;
    const int bx   = blockIdx.x;

    if (bx < 256) {
        uint32_t* WL = smp + PF_WL_V;
        const int b   = bx >> 6;
        const int px0 = ((bx >> 1) & 31) << 7;
        const int cb  = (bx & 1) << 7;
        const int r0  = wid * 16;

        float cv[16][4];
        #pragma unroll
        for (int n = 0; n < 16; ++n)
            #pragma unroll
            for (int k = 0; k < 4; ++k) cv[n][k] = 0.f;

        for (int chunk = 0; chunk < 4; ++chunk) {
            if (chunk) __syncthreads();
            #pragma unroll
            for (int it = 0; it < 16; ++it) {
                int idx = it * 256 + t;
                int i = idx >> 7, px = idx & 127;
                size_t g = (size_t)(b * CC + chunk * 64 + 2 * i) * NN + px0 + px;
                float x0 = str[g], x1 = str[g + NN];
                __half h0 = __float2half_rn(x0), h1 = __float2half_rn(x1);
                INH[i * 136 + px] = pk2h(h0, h1);
                INL[i * 136 + px] = pk2(x0 - __half2float(h0), x1 - __half2float(h1));
            }
            #pragma unroll
            for (int it = 0; it < 16; ++it) {
                int idx = it * 256 + t;
                int cc = idx >> 5, pr = idx & 31;
                float2 w = *(const float2*)&Wv[(size_t)(cb + cc) * CC + chunk * 64 + 2 * pr];
                __half h0 = __float2half_rn(w.x), h1 = __float2half_rn(w.y);
                WH[cc * 36 + pr] = pk2h(h0, h1);
                WL[cc * 36 + pr] = pk2(w.x - __half2float(h0), w.y - __half2float(h1));
            }
            __syncthreads();

            #pragma unroll
            for (int s = 0; s < 4; ++s) {
                uint32_t ah[4], al[4];
                ah[0] = WH[(r0 + lq) * 36 + 8 * s + lr];
                ah[1] = WH[(r0 + lq + 8) * 36 + 8 * s + lr];
                ah[2] = WH[(r0 + lq) * 36 + 8 * s + lr + 4];
                ah[3] = WH[(r0 + lq + 8) * 36 + 8 * s + lr + 4];
                al[0] = WL[(r0 + lq) * 36 + 8 * s + lr];
                al[1] = WL[(r0 + lq + 8) * 36 + 8 * s + lr];
                al[2] = WL[(r0 + lq) * 36 + 8 * s + lr + 4];
                al[3] = WL[(r0 + lq + 8) * 36 + 8 * s + lr + 4];
                const int ro  = (8 * s + lr) * 136;
                const int ro4 = (8 * s + lr + 4) * 136;
                #pragma unroll
                for (int n = 0; n < 16; ++n) {
                    uint32_t bh0 = INH[ro + 8 * n + lq];
                    uint32_t bh1 = INH[ro4 + 8 * n + lq];
                    uint32_t bl0 = INL[ro + 8 * n + lq];
                    uint32_t bl1 = INL[ro4 + 8 * n + lq];
                    mma16(cv[n], ah, bh0, bh1);
                    mma16(cv[n], al, bh0, bh1);
                    mma16(cv[n], ah, bl0, bl1);
                }
            }
        }

        uint32_t* ov = (uint32_t*)g_vh;
        const int ccr = cb + r0 + lq;
        float b0 = __ldg(&bv[ccr]), b8 = __ldg(&bv[ccr + 8]);
        size_t o0 = ((size_t)(b * CC + ccr) * NN + px0) >> 1;
        size_t o8 = o0 + 8 * (NN / 2);
        #pragma unroll
        for (int n = 0; n < 16; ++n) {
            ov[o0 + 4 * n + lr] = pk2(cv[n][0] + b0, cv[n][1] + b0);
            ov[o8 + 4 * n + lr] = pk2(cv[n][2] + b8, cv[n][3] + b8);
        }
    } else {
        uint32_t* WL = smp + PF_WL_QK;
        const int sub  = bx - 256;
        const int pass = sub >> 7;
        const int sidx = sub & 127;
        const int b    = sidx >> 5;
        const int px0  = (sidx & 31) << 7;
        const int wm   = wid & 3;
        const int wn   = wid >> 2;

        const float* inp = pass ? str : sem;
        const float* Wp  = pass ? Wk  : Wq;
        const float* bp  = pass ? bk  : bq;
        uint32_t* oh = (uint32_t*)(pass ? g_kh : g_qh);
        uint32_t* ol = (uint32_t*)(pass ? g_kl : g_ql);

        #pragma unroll
        for (int it = 0; it < 16; ++it) {
            int idx = it * 256 + t;
            int d = idx >> 7, pr = idx & 127;
            float2 w = *(const float2*)&Wp[d * CC + 2 * pr];
            __half h0 = __float2half_rn(w.x), h1 = __float2half_rn(w.y);
            WH[d * 132 + pr] = pk2h(h0, h1);
            WL[d * 132 + pr] = pk2(w.x - __half2float(h0), w.y - __half2float(h1));
        }

        float cq[2][2][4];
        #pragma unroll
        for (int mm = 0; mm < 2; ++mm)
            #pragma unroll
            for (int n = 0; n < 2; ++n)
                #pragma unroll
                for (int k = 0; k < 4; ++k) cq[mm][n][k] = 0.f;

        for (int chunk = 0; chunk < 4; ++chunk) {
            __syncthreads();
            #pragma unroll
            for (int it = 0; it < 16; ++it) {
                int idx = it * 256 + t;
                int i = idx >> 7, px = idx & 127;
                size_t g = (size_t)(b * CC + chunk * 64 + 2 * i) * NN + px0 + px;
                float x0 = inp[g], x1 = inp[g + NN];
                __half h0 = __float2half_rn(x0), h1 = __float2half_rn(x1);
                INH[i * 136 + px] = pk2h(h0, h1);
                INL[i * 136 + px] = pk2(x0 - __half2float(h0), x1 - __half2float(h1));
            }
            __syncthreads();

            #pragma unroll
            for (int s = 0; s < 4; ++s) {
                uint32_t ah[2][4], al[2][4];
                const int ro  = (8 * s + lr) * 136;
                const int ro4 = (8 * s + lr + 4) * 136;
                #pragma unroll
                for (int mm = 0; mm < 2; ++mm) {
                    int pxm = wm * 32 + mm * 16 + lq;
                    ah[mm][0] = INH[ro + pxm];  ah[mm][1] = INH[ro + pxm + 8];
                    ah[mm][2] = INH[ro4 + pxm]; ah[mm][3] = INH[ro4 + pxm + 8];
                    al[mm][0] = INL[ro + pxm];  al[mm][1] = INL[ro + pxm + 8];
                    al[mm][2] = INL[ro4 + pxm]; al[mm][3] = INL[ro4 + pxm + 8];
                }
                #pragma unroll
                for (int n = 0; n < 2; ++n) {
                    int drow = ((wn * 2 + n) * 8 + lq) * 132 + chunk * 32;
                    uint32_t bh0 = WH[drow + 8 * s + lr];
                    uint32_t bh1 = WH[drow + 8 * s + lr + 4];
                    uint32_t bl0 = WL[drow + 8 * s + lr];
                    uint32_t bl1 = WL[drow + 8 * s + lr + 4];
                    #pragma unroll
                    for (int mm = 0; mm < 2; ++mm) {
                        mma16(cq[mm][n], ah[mm], bh0, bh1);
                        mma16(cq[mm][n], al[mm], bh0, bh1);
                        mma16(cq[mm][n], ah[mm], bl0, bl1);
                    }
                }
            }
        }

        #pragma unroll
        for (int mm = 0; mm < 2; ++mm) {
            #pragma unroll
            for (int n = 0; n < 2; ++n) {
                int pxr = px0 + wm * 32 + mm * 16 + lq;
                int d0  = (wn * 2 + n) * 8 + 2 * lr;
                float b0 = __ldg(&bp[d0]), b1 = __ldg(&bp[d0 + 1]);
                float q0 = cq[mm][n][0] + b0, q1 = cq[mm][n][1] + b1;
                float q2 = cq[mm][n][2] + b0, q3 = cq[mm][n][3] + b1;
                __half h0 = __float2half_rn(q0), h1 = __float2half_rn(q1);
                __half h2 = __float2half_rn(q2), h3 = __float2half_rn(q3);
                size_t i0w = (size_t)(b * NN + pxr) * 16 + (wn * 2 + n) * 4 + lr;
                oh[i0w]       = pk2h(h0, h1);
                ol[i0w]       = pk2(q0 - __half2float(h0), q1 - __half2float(h1));
                oh[i0w + 128] = pk2h(h2, h3);
                ol[i0w + 128] = pk2(q2 - __half2float(h2), q3 - __half2float(h3));
            }
        }
    }
}

// ---------------------------------------------------------------------------
// A: fp16 mma flash attention, 128-keys-per-softmax big tiles.
// 512 thr, grid = 128. 2-term S. K double-buffered, V single, P single.
// ---------------------------------------------------------------------------
#define SQH 0
#define SQL 10240
#define SKB 20480       // 4 x 5120: (buf*2+half)*5120
#define SVB 40960       // 2 halves x 36864
#define SPS 114688      // P: 128 x 256B = 32768
#define SLS 147456
#define SM_AT 149504

__device__ __forceinline__ void load_k2(uint32_t smb, const __half* kh,
                                        int j0, int buf, int t)
{
    int row128 = t >> 2, seg = t & 3;
    int half = row128 >> 6, row = row128 & 63;
    cp16(smb + SKB + (buf * 2 + half) * 5120 + row * 80 + seg * 16,
         kh + (size_t)(j0 + half * 64 + row) * DD + seg * 8);
}
__device__ __forceinline__ void load_v2(uint32_t smb, const __half* vh,
                                        int j0, int t)
{
    #pragma unroll
    for (int i = 0; i < 8; ++i) {
        int idx = i * 512 + t;
        int c = idx >> 4, rest = idx & 15;
        int half = rest >> 3, seg = rest & 7;
        cp16(smb + SVB + half * 36864 + c * 144 + seg * 16,
             vh + (size_t)c * NN + j0 + half * 64 + seg * 8);
    }
}

__global__ void __launch_bounds__(512, 1)
attn_mma_kernel(const float* __restrict__ sem, const float* __restrict__ gammaP,
                float* __restrict__ out)
{
    extern __shared__ char smc[];
    const uint32_t smb = s2u(smc);
    float* red = (float*)(smc + SLS);

    const int t    = threadIdx.x;
    const int lane = t & 31;
    const int wid  = t >> 5;
    const int wm   = wid & 3;
    const int wn   = wid >> 2;
    const int R0   = wm * 32;
    const int J0   = wn * 16;
    const int C0w  = wn * 64;
    const int lq   = lane >> 2;
    const int lr   = lane & 3;
    const int l8   = lane & 7;
    const int gp   = lane >> 3;
    const int pgb  = (gp & 2) >> 1;

    const int b  = blockIdx.x >> 5;
    const int i0 = (blockIdx.x & 31) << 7;

    const __half* khb = g_kh + (size_t)b * NN * DD;
    const __half* vhb = g_vh + (size_t)b * CC * NN;

    // preload Q (hi+lo) and K big-tile 0
    #pragma unroll
    for (int i = 0; i < 2; ++i) {
        int idx = i * 512 + t;
        int row = (idx >> 2) & 127, seg = idx & 3;
        const __half* src = (idx < 512 ? g_qh : g_ql) +
                            ((size_t)(b * NN + i0 + row)) * DD + seg * 8;
        cp16(smb + (idx < 512 ? SQH : SQL) + row * 80 + seg * 16, src);
    }
    load_k2(smb, khb, 0, 0, t);
    cp_commit();
    cp_wait0();
    __syncthreads();

    float oacc[2][8][4];
    #pragma unroll
    for (int m = 0; m < 2; ++m)
        #pragma unroll
        for (int n = 0; n < 8; ++n)
            #pragma unroll
            for (int k = 0; k < 4; ++k) oacc[m][n][k] = 0.f;
    float lsum[4] = {0.f, 0.f, 0.f, 0.f};
    float mrun[4] = {-1e30f, -1e30f, -1e30f, -1e30f};

    for (int kt = 0; kt < NT2; ++kt) {
        const int buf = kt & 1;
        // prefetch K(kt+1); load V(kt)
        if (kt + 1 < NT2)
            load_k2(smb, khb, (kt + 1) * KT2, buf ^ 1, t);
        load_v2(smb, vhb, kt * KT2, t);
        cp_commit();

        // ---- S = Q K^T over 128 keys (2-term), sacc[m][half*2+n] ----
        float sacc[2][4][4];
        #pragma unroll
        for (int m = 0; m < 2; ++m)
            #pragma unroll
            for (int jn = 0; jn < 4; ++jn)
                #pragma unroll
                for (int k = 0; k < 4; ++k) sacc[m][jn][k] = 0.f;

        #pragma unroll
        for (int s = 0; s < 2; ++s) {
            uint32_t qh[2][4], ql[2][4];
            #pragma unroll
            for (int m = 0; m < 2; ++m) {
                int qrow = R0 + 16 * m + l8 + ((gp & 1) << 3);
                int qcol = 16 * s + ((gp & 2) << 2);
                uint32_t qa = smb + SQH + (qrow * 40 + qcol) * 2;
                LDSM4(qh[m], qa);
                LDSM4(ql[m], qa + (SQL - SQH));
            }
            int krow = J0 + l8 + ((gp & 2) << 2);
            int kcol = 16 * s + ((gp & 1) << 3);
            #pragma unroll
            for (int half = 0; half < 2; ++half) {
                uint32_t kbase = smb + SKB + (buf * 2 + half) * 5120;
                uint32_t kh[4];
                LDSM4(kh, kbase + (krow * 40 + kcol) * 2);
                #pragma unroll
                for (int n = 0; n < 2; ++n) {
                    #pragma unroll
                    for (int m = 0; m < 2; ++m) {
                        mma16(sacc[m][half * 2 + n], qh[m], kh[2 * n], kh[2 * n + 1]);
                        mma16(sacc[m][half * 2 + n], ql[m], kh[2 * n], kh[2 * n + 1]);
                    }
                }
            }
        }

        // ---- per-tile max partials ----
        float smax[4];
        #pragma unroll
        for (int m = 0; m < 2; ++m) {
            float a = -1e30f, c = -1e30f;
            #pragma unroll
            for (int jn = 0; jn < 4; ++jn) {
                a = fmaxf(a, fmaxf(sacc[m][jn][0], sacc[m][jn][1]));
                c = fmaxf(c, fmaxf(sacc[m][jn][2], sacc[m][jn][3]));
            }
            smax[2 * m] = a;
            smax[2 * m + 1] = c;
        }
        #pragma unroll
        for (int i = 0; i < 4; ++i) {
            smax[i] = fmaxf(smax[i], __shfl_xor_sync(0xFFFFFFFFu, smax[i], 1));
            smax[i] = fmaxf(smax[i], __shfl_xor_sync(0xFFFFFFFFu, smax[i], 2));
        }
        if (lr == 0) {
            #pragma unroll
            for (int i = 0; i < 4; ++i)
                red[wn * 128 + R0 + 8 * i + lq] = smax[i];
        }
        __syncthreads();   // sync A

        // ---- running max, f, rescale oacc ----
        float f[4];
        #pragma unroll
        for (int i = 0; i < 4; ++i) {
            int r = R0 + 8 * i + lq;
            float mt = fmaxf(fmaxf(red[r], red[128 + r]),
                             fmaxf(red[256 + r], red[384 + r]));
            float mn = fmaxf(mrun[i], mt);
            f[i] = __expf(mrun[i] - mn);
            mrun[i] = mn;
            lsum[i] *= f[i];
        }
        if (kt > 0 && (f[0] < 1.f || f[1] < 1.f || f[2] < 1.f || f[3] < 1.f)) {
            #pragma unroll
            for (int m = 0; m < 2; ++m)
                #pragma unroll
                for (int n = 0; n < 8; ++n) {
                    oacc[m][n][0] *= f[2 * m];
                    oacc[m][n][1] *= f[2 * m];
                    oacc[m][n][2] *= f[2 * m + 1];
                    oacc[m][n][3] *= f[2 * m + 1];
                }
        }

        // ---- exp(s - m), l partials, store P (16-chunk swizzle, pitch 256B) ----
        #pragma unroll
        for (int m = 0; m < 2; ++m) {
            int r = R0 + 16 * m + lq;
            #pragma unroll
            for (int jn = 0; jn < 4; ++jn) {
                int h = (jn >> 1) * 8 + wn * 2 + (jn & 1);
                float p0 = __expf(sacc[m][jn][0] - mrun[2 * m]);
                float p1 = __expf(sacc[m][jn][1] - mrun[2 * m]);
                float p2 = __expf(sacc[m][jn][2] - mrun[2 * m + 1]);
                float p3 = __expf(sacc[m][jn][3] - mrun[2 * m + 1]);
                lsum[2 * m]     += p0 + p1;
                lsum[2 * m + 1] += p2 + p3;
                uint32_t a0 = smb + SPS + r * 256 + ((h ^ lq) << 4) + lr * 4;
                asm volatile("st.shared.b32 [%0], %1;" :: "r"(a0), "r"(pk2(p0, p1)) : "memory");
                asm volatile("st.shared.b32 [%0], %1;" :: "r"(a0 + 2048), "r"(pk2(p2, p3)) : "memory");
            }
        }
        cp_wait0();
        __syncthreads();   // sync B

        // ---- PV over 128 keys ----
        #pragma unroll
        for (int kk = 0; kk < 8; ++kk) {
            uint32_t pa[2][4];
            #pragma unroll
            for (int m = 0; m < 2; ++m) {
                int prow = R0 + 16 * m + l8 + ((gp & 1) << 3);
                int pch  = 2 * kk + pgb;
                uint32_t paadr = smb + SPS + prow * 256 + ((pch ^ (prow & 7)) << 4);
                LDSM4(pa[m], paadr);
            }
            const int half = kk >> 2;
            const int vco  = 16 * (kk & 3) + ((gp & 1) << 3);
            const uint32_t vb = smb + SVB + half * 36864;
            #pragma unroll
            for (int np = 0; np < 4; ++np) {
                int vrow = C0w + 16 * np + l8 + ((gp & 2) << 2);
                uint32_t va = vb + (vrow * 72 + vco) * 2;
                uint32_t vv[4];
                LDSM4(vv, va);
                mma16(oacc[0][2 * np],     pa[0], vv[0], vv[1]);
                mma16(oacc[0][2 * np + 1], pa[0], vv[2], vv[3]);
                mma16(oacc[1][2 * np],     pa[1], vv[0], vv[1]);
                mma16(oacc[1][2 * np + 1], pa[1], vv[2], vv[3]);
            }
        }
        __syncthreads();   // sync C (P and V reusable)
    }

    // ---- l reduction ----
    #pragma unroll
    for (int i = 0; i < 4; ++i) {
        lsum[i] += __shfl_xor_sync(0xFFFFFFFFu, lsum[i], 1);
        lsum[i] += __shfl_xor_sync(0xFFFFFFFFu, lsum[i], 2);
    }
    if (lr == 0) {
        #pragma unroll
        for (int i = 0; i < 4; ++i)
            red[wn * 128 + R0 + 8 * i + lq] = lsum[i];
    }
    __syncthreads();

    float linv[4];
    #pragma unroll
    for (int i = 0; i < 4; ++i) {
        int r = R0 + 8 * i + lq;
        linv[i] = 1.f / (red[r] + red[128 + r] + red[256 + r] + red[384 + r]);
    }

    // ---- epilogue ----
    const float g = gammaP[0];
    #pragma unroll
    for (int m = 0; m < 2; ++m) {
        #pragma unroll
        for (int n = 0; n < 8; ++n) {
            int ch = C0w + 8 * n + 2 * lr;
            size_t ia = ((size_t)(b * CC + ch)) * NN + i0 + R0 + 16 * m + lq;
            out[ia]          = g * oacc[m][n][0] * linv[2 * m]     + sem[ia];
            out[ia + NN]     = g * oacc[m][n][1] * linv[2 * m]     + sem[ia + NN];
            out[ia + 8]      = g * oacc[m][n][2] * linv[2 * m + 1] + sem[ia + 8];
            out[ia + NN + 8] = g * oacc[m][n][3] * linv[2 * m + 1] + sem[ia + NN + 8];
        }
    }
}

// ---------------------------------------------------------------------------
extern "C" void kernel_launch(void* const* d_in, const int* in_sizes, int n_in,
                              void* d_out, int out_size)
{
    const float* sem = (const float*)d_in[0];
    const float* str = (const float*)d_in[1];
    const float* Wq  = (const float*)d_in[2];
    const float* bq  = (const float*)d_in[3];
    const float* Wk  = (const float*)d_in[4];
    const float* bk  = (const float*)d_in[5];
    const float* Wv  = (const float*)d_in[6];
    const float* bv  = (const float*)d_in[7];
    const float* gam = (const float*)d_in[8];
    float* out = (float*)d_out;

    const int smem_pf = PF_TOT * 4;
    const int smem_at = SM_AT;

    cudaFuncSetAttribute(proj_fused,
        cudaFuncAttributeMaxDynamicSharedMemorySize, smem_pf);
    cudaFuncSetAttribute(attn_mma_kernel,
        cudaFuncAttributeMaxDynamicSharedMemorySize, smem_at);

    proj_fused<<<512, 256, smem_pf>>>(sem, str, Wq, bq, Wk, bk, Wv, bv);
    attn_mma_kernel<<<BB * (NN / 128), 512, smem_at>>>(sem, gam, out);
}

// round 16
// speedup vs baseline: 1.1328x; 1.0202x over previous
#include <cuda_runtime.h>
#include <cuda_fp16.h>
#include <cstdint>

#define BB 4
#define CC 256
#define NN 4096
#define DD 32
#define KT2 128
#define NT2 (NN / KT2)   // 32 big tiles

// Scratch: pre-split half precision operands
__device__ __half g_qh[BB * NN * DD];
__device__ __half g_ql[BB * NN * DD];
__device__ __half g_kh[BB * NN * DD];
__device__ __half g_kl[BB * NN * DD];   // produced by proj; unused by attn
__device__ __half g_vh[BB * CC * NN];   // [B][C][N]

// ---------------------------------------------------------------------------
__device__ __forceinline__ void mma16(float* d, const uint32_t* a,
                                      uint32_t b0, uint32_t b1) {
    asm("mma.sync.aligned.m16n8k16.row.col.f32.f16.f16.f32 "
        "{%0,%1,%2,%3},{%4,%5,%6,%7},{%8,%9},{%0,%1,%2,%3};"
        : "+f"(d[0]), "+f"(d[1]), "+f"(d[2]), "+f"(d[3])
        : "r"(a[0]), "r"(a[1]), "r"(a[2]), "r"(a[3]), "r"(b0), "r"(b1));
}
#define LDSM4(r, addr) \
    asm volatile("ldmatrix.sync.aligned.m8n8.x4.shared.b16 {%0,%1,%2,%3}, [%4];" \
        : "=r"((r)[0]), "=r"((r)[1]), "=r"((r)[2]), "=r"((r)[3]) : "r"(addr))

__device__ __forceinline__ uint32_t s2u(const void* p) {
    uint32_t a;
    asm("{ .reg .u64 t; cvta.to.shared.u64 t, %1; cvt.u32.u64 %0, t; }"
        : "=r"(a) : "l"(p));
    return a;
}
__device__ __forceinline__ void cp16(uint32_t dst, const void* src) {
    asm volatile("cp.async.cg.shared.global [%0], [%1], 16;"
                 :: "r"(dst), "l"(src) : "memory");
}
__device__ __forceinline__ void cp_commit() {
    asm volatile("cp.async.commit_group;" ::: "memory");
}
__device__ __forceinline__ void cp_wait0() {
    asm volatile("cp.async.wait_group 0;" ::: "memory");
}
__device__ __forceinline__ void cp_wait1() {
    asm volatile("cp.async.wait_group 1;" ::: "memory");
}
__device__ __forceinline__ uint32_t pk2(float a, float b) {
    __half2 h = __floats2half2_rn(a, b);
    return *(uint32_t*)&h;
}
__device__ __forceinline__ uint32_t pk2h(__half a, __half b) {
    __half2 h = __halves2half2(a, b);
    return *(uint32_t*)&h;
}

// ===========================================================================
// Fused projections (UNCHANGED from R10). grid = 512 x 256 thr, occ 2.
// ===========================================================================
#define PF_INH 0
#define PF_INL 4352
#define PF_WH  8704
#define PF_WL_QK 12928
#define PF_WL_V  13312
#define PF_TOT 17920

__global__ void __launch_bounds__(256, 2)
proj_fused(const float* __restrict__ sem, const float* __restrict__ str,
           const float* __restrict__ Wq, const float* __restrict__ bq,
           const float* __restrict__ Wk, const float* __restrict__ bk,
           const float* __restrict__ Wv, const float* __restrict__ bv)
{
    extern __shared__ uint32_t smp[];
    uint32_t* INH = smp + PF_INH;
    uint32_t* INL = smp + PF_INL;
    uint32_t* WH  = smp + PF_WH;

    const int t    = threadIdx.x;
    const int lane = t & 31;
    const int wid  = t >> 5;
    const int lq   = lane >> 2;
    const int lr   = lane & 3;
    const int bx   = blockIdx.x;

    if (bx < 256) {
        uint32_t* WL = smp + PF_WL_V;
        const int b   = bx >> 6;
        const int px0 = ((bx >> 1) & 31) << 7;
        const int cb  = (bx & 1) << 7;
        const int r0  = wid * 16;

        float cv[16][4];
        #pragma unroll
        for (int n = 0; n < 16; ++n)
            #pragma unroll
            for (int k = 0; k < 4; ++k) cv[n][k] = 0.f;

        for (int chunk = 0; chunk < 4; ++chunk) {
            if (chunk) __syncthreads();
            #pragma unroll
            for (int it = 0; it < 16; ++it) {
                int idx = it * 256 + t;
                int i = idx >> 7, px = idx & 127;
                size_t g = (size_t)(b * CC + chunk * 64 + 2 * i) * NN + px0 + px;
                float x0 = str[g], x1 = str[g + NN];
                __half h0 = __float2half_rn(x0), h1 = __float2half_rn(x1);
                INH[i * 136 + px] = pk2h(h0, h1);
                INL[i * 136 + px] = pk2(x0 - __half2float(h0), x1 - __half2float(h1));
            }
            #pragma unroll
            for (int it = 0; it < 16; ++it) {
                int idx = it * 256 + t;
                int cc = idx >> 5, pr = idx & 31;
                float2 w = *(const float2*)&Wv[(size_t)(cb + cc) * CC + chunk * 64 + 2 * pr];
                __half h0 = __float2half_rn(w.x), h1 = __float2half_rn(w.y);
                WH[cc * 36 + pr] = pk2h(h0, h1);
                WL[cc * 36 + pr] = pk2(w.x - __half2float(h0), w.y - __half2float(h1));
            }
            __syncthreads();

            #pragma unroll
            for (int s = 0; s < 4; ++s) {
                uint32_t ah[4], al[4];
                ah[0] = WH[(r0 + lq) * 36 + 8 * s + lr];
                ah[1] = WH[(r0 + lq + 8) * 36 + 8 * s + lr];
                ah[2] = WH[(r0 + lq) * 36 + 8 * s + lr + 4];
                ah[3] = WH[(r0 + lq + 8) * 36 + 8 * s + lr + 4];
                al[0] = WL[(r0 + lq) * 36 + 8 * s + lr];
                al[1] = WL[(r0 + lq + 8) * 36 + 8 * s + lr];
                al[2] = WL[(r0 + lq) * 36 + 8 * s + lr + 4];
                al[3] = WL[(r0 + lq + 8) * 36 + 8 * s + lr + 4];
                const int ro  = (8 * s + lr) * 136;
                const int ro4 = (8 * s + lr + 4) * 136;
                #pragma unroll
                for (int n = 0; n < 16; ++n) {
                    uint32_t bh0 = INH[ro + 8 * n + lq];
                    uint32_t bh1 = INH[ro4 + 8 * n + lq];
                    uint32_t bl0 = INL[ro + 8 * n + lq];
                    uint32_t bl1 = INL[ro4 + 8 * n + lq];
                    mma16(cv[n], ah, bh0, bh1);
                    mma16(cv[n], al, bh0, bh1);
                    mma16(cv[n], ah, bl0, bl1);
                }
            }
        }

        uint32_t* ov = (uint32_t*)g_vh;
        const int ccr = cb + r0 + lq;
        float b0 = __ldg(&bv[ccr]), b8 = __ldg(&bv[ccr + 8]);
        size_t o0 = ((size_t)(b * CC + ccr) * NN + px0) >> 1;
        size_t o8 = o0 + 8 * (NN / 2);
        #pragma unroll
        for (int n = 0; n < 16; ++n) {
            ov[o0 + 4 * n + lr] = pk2(cv[n][0] + b0, cv[n][1] + b0);
            ov[o8 + 4 * n + lr] = pk2(cv[n][2] + b8, cv[n][3] + b8);
        }
    } else {
        uint32_t* WL = smp + PF_WL_QK;
        const int sub  = bx - 256;
        const int pass = sub >> 7;
        const int sidx = sub & 127;
        const int b    = sidx >> 5;
        const int px0  = (sidx & 31) << 7;
        const int wm   = wid & 3;
        const int wn   = wid >> 2;

        const float* inp = pass ? str : sem;
        const float* Wp  = pass ? Wk  : Wq;
        const float* bp  = pass ? bk  : bq;
        uint32_t* oh = (uint32_t*)(pass ? g_kh : g_qh);
        uint32_t* ol = (uint32_t*)(pass ? g_kl : g_ql);

        #pragma unroll
        for (int it = 0; it < 16; ++it) {
            int idx = it * 256 + t;
            int d = idx >> 7, pr = idx & 127;
            float2 w = *(const float2*)&Wp[d * CC + 2 * pr];
            __half h0 = __float2half_rn(w.x), h1 = __float2half_rn(w.y);
            WH[d * 132 + pr] = pk2h(h0, h1);
            WL[d * 132 + pr] = pk2(w.x - __half2float(h0), w.y - __half2float(h1));
        }

        float cq[2][2][4];
        #pragma unroll
        for (int mm = 0; mm < 2; ++mm)
            #pragma unroll
            for (int n = 0; n < 2; ++n)
                #pragma unroll
                for (int k = 0; k < 4; ++k) cq[mm][n][k] = 0.f;

        for (int chunk = 0; chunk < 4; ++chunk) {
            __syncthreads();
            #pragma unroll
            for (int it = 0; it < 16; ++it) {
                int idx = it * 256 + t;
                int i = idx >> 7, px = idx & 127;
                size_t g = (size_t)(b * CC + chunk * 64 + 2 * i) * NN + px0 + px;
                float x0 = inp[g], x1 = inp[g + NN];
                __half h0 = __float2half_rn(x0), h1 = __float2half_rn(x1);
                INH[i * 136 + px] = pk2h(h0, h1);
                INL[i * 136 + px] = pk2(x0 - __half2float(h0), x1 - __half2float(h1));
            }
            __syncthreads();

            #pragma unroll
            for (int s = 0; s < 4; ++s) {
                uint32_t ah[2][4], al[2][4];
                const int ro  = (8 * s + lr) * 136;
                const int ro4 = (8 * s + lr + 4) * 136;
                #pragma unroll
                for (int mm = 0; mm < 2; ++mm) {
                    int pxm = wm * 32 + mm * 16 + lq;
                    ah[mm][0] = INH[ro + pxm];  ah[mm][1] = INH[ro + pxm + 8];
                    ah[mm][2] = INH[ro4 + pxm]; ah[mm][3] = INH[ro4 + pxm + 8];
                    al[mm][0] = INL[ro + pxm];  al[mm][1] = INL[ro + pxm + 8];
                    al[mm][2] = INL[ro4 + pxm]; al[mm][3] = INL[ro4 + pxm + 8];
                }
                #pragma unroll
                for (int n = 0; n < 2; ++n) {
                    int drow = ((wn * 2 + n) * 8 + lq) * 132 + chunk * 32;
                    uint32_t bh0 = WH[drow + 8 * s + lr];
                    uint32_t bh1 = WH[drow + 8 * s + lr + 4];
                    uint32_t bl0 = WL[drow + 8 * s + lr];
                    uint32_t bl1 = WL[drow + 8 * s + lr + 4];
                    #pragma unroll
                    for (int mm = 0; mm < 2; ++mm) {
                        mma16(cq[mm][n], ah[mm], bh0, bh1);
                        mma16(cq[mm][n], al[mm], bh0, bh1);
                        mma16(cq[mm][n], ah[mm], bl0, bl1);
                    }
                }
            }
        }

        #pragma unroll
        for (int mm = 0; mm < 2; ++mm) {
            #pragma unroll
            for (int n = 0; n < 2; ++n) {
                int pxr = px0 + wm * 32 + mm * 16 + lq;
                int d0  = (wn * 2 + n) * 8 + 2 * lr;
                float b0 = __ldg(&bp[d0]), b1 = __ldg(&bp[d0 + 1]);
                float q0 = cq[mm][n][0] + b0, q1 = cq[mm][n][1] + b1;
                float q2 = cq[mm][n][2] + b0, q3 = cq[mm][n][3] + b1;
                __half h0 = __float2half_rn(q0), h1 = __float2half_rn(q1);
                __half h2 = __float2half_rn(q2), h3 = __float2half_rn(q3);
                size_t i0w = (size_t)(b * NN + pxr) * 16 + (wn * 2 + n) * 4 + lr;
                oh[i0w]       = pk2h(h0, h1);
                ol[i0w]       = pk2(q0 - __half2float(h0), q1 - __half2float(h1));
                oh[i0w + 128] = pk2h(h2, h3);
                ol[i0w + 128] = pk2(q2 - __half2float(h2), q3 - __half2float(h3));
            }
        }
    }
}

// ---------------------------------------------------------------------------
// A: fp16 mma flash attention, 128-key tiles, V double-buffered,
// 2 barriers/tile. 512 thr, grid = 128.
// smem: Q 20480 | K 4x5120 | V 2x73728 | P 32768 | red 2048 = 223232 B
// ---------------------------------------------------------------------------
#define SQH 0
#define SQL 10240
#define SKB 20480
#define SVB 40960
#define VBUF2 73728
#define SPS 188416
#define SLS 221184
#define SM_AT 223232

__device__ __forceinline__ void load_k2(uint32_t smb, const __half* kh,
                                        int j0, int buf, int t)
{
    int row128 = t >> 2, seg = t & 3;
    int half = row128 >> 6, row = row128 & 63;
    cp16(smb + SKB + (buf * 2 + half) * 5120 + row * 80 + seg * 16,
         kh + (size_t)(j0 + half * 64 + row) * DD + seg * 8);
}
__device__ __forceinline__ void load_v2(uint32_t smb, const __half* vh,
                                        int j0, int vbuf, int t)
{
    #pragma unroll
    for (int i = 0; i < 8; ++i) {
        int idx = i * 512 + t;
        int c = idx >> 4, rest = idx & 15;
        int half = rest >> 3, seg = rest & 7;
        cp16(smb + SVB + vbuf * VBUF2 + half * 36864 + c * 144 + seg * 16,
             vh + (size_t)c * NN + j0 + half * 64 + seg * 8);
    }
}

__global__ void __launch_bounds__(512, 1)
attn_mma_kernel(const float* __restrict__ sem, const float* __restrict__ gammaP,
                float* __restrict__ out)
{
    extern __shared__ char smc[];
    const uint32_t smb = s2u(smc);
    float* red = (float*)(smc + SLS);

    const int t    = threadIdx.x;
    const int lane = t & 31;
    const int wid  = t >> 5;
    const int wm   = wid & 3;
    const int wn   = wid >> 2;
    const int R0   = wm * 32;
    const int J0   = wn * 16;
    const int C0w  = wn * 64;
    const int lq   = lane >> 2;
    const int lr   = lane & 3;
    const int l8   = lane & 7;
    const int gp   = lane >> 3;
    const int pgb  = (gp & 2) >> 1;

    const int b  = blockIdx.x >> 5;
    const int i0 = (blockIdx.x & 31) << 7;

    const __half* khb = g_kh + (size_t)b * NN * DD;
    const __half* vhb = g_vh + (size_t)b * CC * NN;

    // preload Q (hi+lo), K(0), V(0)
    #pragma unroll
    for (int i = 0; i < 2; ++i) {
        int idx = i * 512 + t;
        int row = (idx >> 2) & 127, seg = idx & 3;
        const __half* src = (idx < 512 ? g_qh : g_ql) +
                            ((size_t)(b * NN + i0 + row)) * DD + seg * 8;
        cp16(smb + (idx < 512 ? SQH : SQL) + row * 80 + seg * 16, src);
    }
    load_k2(smb, khb, 0, 0, t);
    load_v2(smb, vhb, 0, 0, t);
    cp_commit();
    cp_wait0();
    __syncthreads();

    float oacc[2][8][4];
    #pragma unroll
    for (int m = 0; m < 2; ++m)
        #pragma unroll
        for (int n = 0; n < 8; ++n)
            #pragma unroll
            for (int k = 0; k < 4; ++k) oacc[m][n][k] = 0.f;
    float lsum[4] = {0.f, 0.f, 0.f, 0.f};
    float mrun[4] = {-1e30f, -1e30f, -1e30f, -1e30f};

    for (int kt = 0; kt < NT2; ++kt) {
        const int buf = kt & 1;
        // K(kt+1) prefetch (safe: all warps past sync-B(kt-1) => S(kt-1) done)
        if (kt + 1 < NT2) {
            load_k2(smb, khb, (kt + 1) * KT2, buf ^ 1, t);
            cp_commit();
        }

        // ---- S = Q K^T over 128 keys (2-term) ----
        float sacc[2][4][4];
        #pragma unroll
        for (int m = 0; m < 2; ++m)
            #pragma unroll
            for (int jn = 0; jn < 4; ++jn)
                #pragma unroll
                for (int k = 0; k < 4; ++k) sacc[m][jn][k] = 0.f;

        #pragma unroll
        for (int s = 0; s < 2; ++s) {
            uint32_t qh[2][4], ql[2][4];
            #pragma unroll
            for (int m = 0; m < 2; ++m) {
                int qrow = R0 + 16 * m + l8 + ((gp & 1) << 3);
                int qcol = 16 * s + ((gp & 2) << 2);
                uint32_t qa = smb + SQH + (qrow * 40 + qcol) * 2;
                LDSM4(qh[m], qa);
                LDSM4(ql[m], qa + (SQL - SQH));
            }
            int krow = J0 + l8 + ((gp & 2) << 2);
            int kcol = 16 * s + ((gp & 1) << 3);
            #pragma unroll
            for (int half = 0; half < 2; ++half) {
                uint32_t kbase = smb + SKB + (buf * 2 + half) * 5120;
                uint32_t kh[4];
                LDSM4(kh, kbase + (krow * 40 + kcol) * 2);
                #pragma unroll
                for (int n = 0; n < 2; ++n) {
                    #pragma unroll
                    for (int m = 0; m < 2; ++m) {
                        mma16(sacc[m][half * 2 + n], qh[m], kh[2 * n], kh[2 * n + 1]);
                        mma16(sacc[m][half * 2 + n], ql[m], kh[2 * n], kh[2 * n + 1]);
                    }
                }
            }
        }

        // ---- per-tile max partials ----
        float smax[4];
        #pragma unroll
        for (int m = 0; m < 2; ++m) {
            float a = -1e30f, c = -1e30f;
            #pragma unroll
            for (int jn = 0; jn < 4; ++jn) {
                a = fmaxf(a, fmaxf(sacc[m][jn][0], sacc[m][jn][1]));
                c = fmaxf(c, fmaxf(sacc[m][jn][2], sacc[m][jn][3]));
            }
            smax[2 * m] = a;
            smax[2 * m + 1] = c;
        }
        #pragma unroll
        for (int i = 0; i < 4; ++i) {
            smax[i] = fmaxf(smax[i], __shfl_xor_sync(0xFFFFFFFFu, smax[i], 1));
            smax[i] = fmaxf(smax[i], __shfl_xor_sync(0xFFFFFFFFu, smax[i], 2));
        }
        if (lr == 0) {
            #pragma unroll
            for (int i = 0; i < 4; ++i)
                red[wn * 128 + R0 + 8 * i + lq] = smax[i];
        }
        __syncthreads();   // sync A  (also: PV(kt-1) complete)

        // V(kt+1) prefetch (safe: PV(kt-1) on buf^1 done at sync A)
        if (kt + 1 < NT2) {
            load_v2(smb, vhb, (kt + 1) * KT2, buf ^ 1, t);
            cp_commit();
        }

        // ---- running max, f, rescale oacc ----
        float f[4];
        #pragma unroll
        for (int i = 0; i < 4; ++i) {
            int r = R0 + 8 * i + lq;
            float mt = fmaxf(fmaxf(red[r], red[128 + r]),
                             fmaxf(red[256 + r], red[384 + r]));
            float mn = fmaxf(mrun[i], mt);
            f[i] = __expf(mrun[i] - mn);
            mrun[i] = mn;
            lsum[i] *= f[i];
        }
        if (kt > 0 && (f[0] < 1.f || f[1] < 1.f || f[2] < 1.f || f[3] < 1.f)) {
            #pragma unroll
            for (int m = 0; m < 2; ++m)
                #pragma unroll
                for (int n = 0; n < 8; ++n) {
                    oacc[m][n][0] *= f[2 * m];
                    oacc[m][n][1] *= f[2 * m];
                    oacc[m][n][2] *= f[2 * m + 1];
                    oacc[m][n][3] *= f[2 * m + 1];
                }
        }

        // ---- exp(s - m), l partials, store P ----
        #pragma unroll
        for (int m = 0; m < 2; ++m) {
            int r = R0 + 16 * m + lq;
            #pragma unroll
            for (int jn = 0; jn < 4; ++jn) {
                int h = (jn >> 1) * 8 + wn * 2 + (jn & 1);
                float p0 = __expf(sacc[m][jn][0] - mrun[2 * m]);
                float p1 = __expf(sacc[m][jn][1] - mrun[2 * m]);
                float p2 = __expf(sacc[m][jn][2] - mrun[2 * m + 1]);
                float p3 = __expf(sacc[m][jn][3] - mrun[2 * m + 1]);
                lsum[2 * m]     += p0 + p1;
                lsum[2 * m + 1] += p2 + p3;
                uint32_t a0 = smb + SPS + r * 256 + ((h ^ lq) << 4) + lr * 4;
                asm volatile("st.shared.b32 [%0], %1;" :: "r"(a0), "r"(pk2(p0, p1)) : "memory");
                asm volatile("st.shared.b32 [%0], %1;" :: "r"(a0 + 2048), "r"(pk2(p2, p3)) : "memory");
            }
        }
        // wait: all groups except V(kt+1)  -> K(kt+1) and V(kt) resident
        if (kt + 1 < NT2) cp_wait1(); else cp_wait0();
        __syncthreads();   // sync B

        // ---- PV over 128 keys from V[buf] ----
        const uint32_t vbb = smb + SVB + buf * VBUF2;
        #pragma unroll
        for (int kk = 0; kk < 8; ++kk) {
            uint32_t pa[2][4];
            #pragma unroll
            for (int m = 0; m < 2; ++m) {
                int prow = R0 + 16 * m + l8 + ((gp & 1) << 3);
                int pch  = 2 * kk + pgb;
                uint32_t paadr = smb + SPS + prow * 256 + ((pch ^ (prow & 7)) << 4);
                LDSM4(pa[m], paadr);
            }
            const int half = kk >> 2;
            const int vco  = 16 * (kk & 3) + ((gp & 1) << 3);
            const uint32_t vb = vbb + half * 36864;
            #pragma unroll
            for (int np = 0; np < 4; ++np) {
                int vrow = C0w + 16 * np + l8 + ((gp & 2) << 2);
                uint32_t va = vb + (vrow * 72 + vco) * 2;
                uint32_t vv[4];
                LDSM4(vv, va);
                mma16(oacc[0][2 * np],     pa[0], vv[0], vv[1]);
                mma16(oacc[0][2 * np + 1], pa[0], vv[2], vv[3]);
                mma16(oacc[1][2 * np],     pa[1], vv[0], vv[1]);
                mma16(oacc[1][2 * np + 1], pa[1], vv[2], vv[3]);
            }
        }
        // no sync C: P writes gated by sync A(kt+1); V writes go to other buf
    }

    // ---- l reduction ----
    #pragma unroll
    for (int i = 0; i < 4; ++i) {
        lsum[i] += __shfl_xor_sync(0xFFFFFFFFu, lsum[i], 1);
        lsum[i] += __shfl_xor_sync(0xFFFFFFFFu, lsum[i], 2);
    }
    __syncthreads();   // red reads from f-phase all done (redundant-safe)
    if (lr == 0) {
        #pragma unroll
        for (int i = 0; i < 4; ++i)
            red[wn * 128 + R0 + 8 * i + lq] = lsum[i];
    }
    __syncthreads();

    float linv[4];
    #pragma unroll
    for (int i = 0; i < 4; ++i) {
        int r = R0 + 8 * i + lq;
        linv[i] = 1.f / (red[r] + red[128 + r] + red[256 + r] + red[384 + r]);
    }

    // ---- epilogue ----
    const float g = gammaP[0];
    #pragma unroll
    for (int m = 0; m < 2; ++m) {
        #pragma unroll
        for (int n = 0; n < 8; ++n) {
            int ch = C0w + 8 * n + 2 * lr;
            size_t ia = ((size_t)(b * CC + ch)) * NN + i0 + R0 + 16 * m + lq;
            out[ia]          = g * oacc[m][n][0] * linv[2 * m]     + sem[ia];
            out[ia + NN]     = g * oacc[m][n][1] * linv[2 * m]     + sem[ia + NN];
            out[ia + 8]      = g * oacc[m][n][2] * linv[2 * m + 1] + sem[ia + 8];
            out[ia + NN + 8] = g * oacc[m][n][3] * linv[2 * m + 1] + sem[ia + NN + 8];
        }
    }
}

// ---------------------------------------------------------------------------
extern "C" void kernel_launch(void* const* d_in, const int* in_sizes, int n_in,
                              void* d_out, int out_size)
{
    const float* sem = (const float*)d_in[0];
    const float* str = (const float*)d_in[1];
    const float* Wq  = (const float*)d_in[2];
    const float* bq  = (const float*)d_in[3];
    const float* Wk  = (const float*)d_in[4];
    const float* bk  = (const float*)d_in[5];
    const float* Wv  = (const float*)d_in[6];
    const float* bv  = (const float*)d_in[7];
    const float* gam = (const float*)d_in[8];
    float* out = (float*)d_out;

    const int smem_pf = PF_TOT * 4;
    const int smem_at = SM_AT;

    cudaFuncSetAttribute(proj_fused,
        cudaFuncAttributeMaxDynamicSharedMemorySize, smem_pf);
    cudaFuncSetAttribute(attn_mma_kernel,
        cudaFuncAttributeMaxDynamicSharedMemorySize, smem_at);

    proj_fused<<<512, 256, smem_pf>>>(sem, str, Wq, bq, Wk, bk, Wv, bv);
    attn_mma_kernel<<<BB * (NN / 128), 512, smem_at>>>(sem, gam, out);
}

// round 17
// speedup vs baseline: 1.1420x; 1.0081x over previous
#include <cuda_runtime.h>
#include <cuda_fp16.h>
#include <cstdint>

#define BB 4
#define CC 256
#define NN 4096
#define DD 32
#define KT2 128
#define NT2 (NN / KT2)   // 32 big tiles
#define LOG2E 1.4426950408889634f

// Scratch: pre-split half precision operands (q pre-scaled by log2e)
__device__ __half g_qh[BB * NN * DD];
__device__ __half g_ql[BB * NN * DD];
__device__ __half g_kh[BB * NN * DD];
__device__ __half g_kl[BB * NN * DD];   // produced by proj; unused by attn
__device__ __half g_vh[BB * CC * NN];   // [B][C][N]

// ---------------------------------------------------------------------------
__device__ __forceinline__ void mma16(float* d, const uint32_t* a,
                                      uint32_t b0, uint32_t b1) {
    asm("mma.sync.aligned.m16n8k16.row.col.f32.f16.f16.f32 "
        "{%0,%1,%2,%3},{%4,%5,%6,%7},{%8,%9},{%0,%1,%2,%3};"
        : "+f"(d[0]), "+f"(d[1]), "+f"(d[2]), "+f"(d[3])
        : "r"(a[0]), "r"(a[1]), "r"(a[2]), "r"(a[3]), "r"(b0), "r"(b1));
}
#define LDSM4(r, addr) \
    asm volatile("ldmatrix.sync.aligned.m8n8.x4.shared.b16 {%0,%1,%2,%3}, [%4];" \
        : "=r"((r)[0]), "=r"((r)[1]), "=r"((r)[2]), "=r"((r)[3]) : "r"(addr))
#define BARN(id) \
    asm volatile("bar.sync %0, 128;" :: "r"(id) : "memory")

__device__ __forceinline__ float ex2(float x) {
    float y;
    asm("ex2.approx.f32 %0, %1;" : "=f"(y) : "f"(x));
    return y;
}
__device__ __forceinline__ uint32_t s2u(const void* p) {
    uint32_t a;
    asm("{ .reg .u64 t; cvta.to.shared.u64 t, %1; cvt.u32.u64 %0, t; }"
        : "=r"(a) : "l"(p));
    return a;
}
__device__ __forceinline__ void cp16(uint32_t dst, const void* src) {
    asm volatile("cp.async.cg.shared.global [%0], [%1], 16;"
                 :: "r"(dst), "l"(src) : "memory");
}
__device__ __forceinline__ void cp_commit() {
    asm volatile("cp.async.commit_group;" ::: "memory");
}
__device__ __forceinline__ void cp_wait0() {
    asm volatile("cp.async.wait_group 0;" ::: "memory");
}
__device__ __forceinline__ void cp_wait1() {
    asm volatile("cp.async.wait_group 1;" ::: "memory");
}
__device__ __forceinline__ uint32_t pk2(float a, float b) {
    __half2 h = __floats2half2_rn(a, b);
    return *(uint32_t*)&h;
}
__device__ __forceinline__ uint32_t pk2h(__half a, __half b) {
    __half2 h = __halves2half2(a, b);
    return *(uint32_t*)&h;
}

// ===========================================================================
// Fused projections. grid = 512 x 256 thr, occ 2. (q scaled by LOG2E)
// ===========================================================================
#define PF_INH 0
#define PF_INL 4352
#define PF_WH  8704
#define PF_WL_QK 12928
#define PF_WL_V  13312
#define PF_TOT 17920

__global__ void __launch_bounds__(256, 2)
proj_fused(const float* __restrict__ sem, const float* __restrict__ str,
           const float* __restrict__ Wq, const float* __restrict__ bq,
           const float* __restrict__ Wk, const float* __restrict__ bk,
           const float* __restrict__ Wv, const float* __restrict__ bv)
{
    extern __shared__ uint32_t smp[];
    uint32_t* INH = smp + PF_INH;
    uint32_t* INL = smp + PF_INL;
    uint32_t* WH  = smp + PF_WH;

    const int t    = threadIdx.x;
    const int lane = t & 31;
    const int wid  = t >> 5;
    const int lq   = lane >> 2;
    const int lr   = lane & 3;
    const int bx   = blockIdx.x;

    if (bx < 256) {
        uint32_t* WL = smp + PF_WL_V;
        const int b   = bx >> 6;
        const int px0 = ((bx >> 1) & 31) << 7;
        const int cb  = (bx & 1) << 7;
        const int r0  = wid * 16;

        float cv[16][4];
        #pragma unroll
        for (int n = 0; n < 16; ++n)
            #pragma unroll
            for (int k = 0; k < 4; ++k) cv[n][k] = 0.f;

        for (int chunk = 0; chunk < 4; ++chunk) {
            if (chunk) __syncthreads();
            #pragma unroll
            for (int it = 0; it < 16; ++it) {
                int idx = it * 256 + t;
                int i = idx >> 7, px = idx & 127;
                size_t g = (size_t)(b * CC + chunk * 64 + 2 * i) * NN + px0 + px;
                float x0 = str[g], x1 = str[g + NN];
                __half h0 = __float2half_rn(x0), h1 = __float2half_rn(x1);
                INH[i * 136 + px] = pk2h(h0, h1);
                INL[i * 136 + px] = pk2(x0 - __half2float(h0), x1 - __half2float(h1));
            }
            #pragma unroll
            for (int it = 0; it < 16; ++it) {
                int idx = it * 256 + t;
                int cc = idx >> 5, pr = idx & 31;
                float2 w = *(const float2*)&Wv[(size_t)(cb + cc) * CC + chunk * 64 + 2 * pr];
                __half h0 = __float2half_rn(w.x), h1 = __float2half_rn(w.y);
                WH[cc * 36 + pr] = pk2h(h0, h1);
                WL[cc * 36 + pr] = pk2(w.x - __half2float(h0), w.y - __half2float(h1));
            }
            __syncthreads();

            #pragma unroll
            for (int s = 0; s < 4; ++s) {
                uint32_t ah[4], al[4];
                ah[0] = WH[(r0 + lq) * 36 + 8 * s + lr];
                ah[1] = WH[(r0 + lq + 8) * 36 + 8 * s + lr];
                ah[2] = WH[(r0 + lq) * 36 + 8 * s + lr + 4];
                ah[3] = WH[(r0 + lq + 8) * 36 + 8 * s + lr + 4];
                al[0] = WL[(r0 + lq) * 36 + 8 * s + lr];
                al[1] = WL[(r0 + lq + 8) * 36 + 8 * s + lr];
                al[2] = WL[(r0 + lq) * 36 + 8 * s + lr + 4];
                al[3] = WL[(r0 + lq + 8) * 36 + 8 * s + lr + 4];
                const int ro  = (8 * s + lr) * 136;
                const int ro4 = (8 * s + lr + 4) * 136;
                #pragma unroll
                for (int n = 0; n < 16; ++n) {
                    uint32_t bh0 = INH[ro + 8 * n + lq];
                    uint32_t bh1 = INH[ro4 + 8 * n + lq];
                    uint32_t bl0 = INL[ro + 8 * n + lq];
                    uint32_t bl1 = INL[ro4 + 8 * n + lq];
                    mma16(cv[n], ah, bh0, bh1);
                    mma16(cv[n], al, bh0, bh1);
                    mma16(cv[n], ah, bl0, bl1);
                }
            }
        }

        uint32_t* ov = (uint32_t*)g_vh;
        const int ccr = cb + r0 + lq;
        float b0 = __ldg(&bv[ccr]), b8 = __ldg(&bv[ccr + 8]);
        size_t o0 = ((size_t)(b * CC + ccr) * NN + px0) >> 1;
        size_t o8 = o0 + 8 * (NN / 2);
        #pragma unroll
        for (int n = 0; n < 16; ++n) {
            ov[o0 + 4 * n + lr] = pk2(cv[n][0] + b0, cv[n][1] + b0);
            ov[o8 + 4 * n + lr] = pk2(cv[n][2] + b8, cv[n][3] + b8);
        }
    } else {
        uint32_t* WL = smp + PF_WL_QK;
        const int sub  = bx - 256;
        const int pass = sub >> 7;
        const int sidx = sub & 127;
        const int b    = sidx >> 5;
        const int px0  = (sidx & 31) << 7;
        const int wm   = wid & 3;
        const int wn   = wid >> 2;

        const float* inp = pass ? str : sem;
        const float* Wp  = pass ? Wk  : Wq;
        const float* bp  = pass ? bk  : bq;
        uint32_t* oh = (uint32_t*)(pass ? g_kh : g_qh);
        uint32_t* ol = (uint32_t*)(pass ? g_kl : g_ql);
        const float scl = pass ? 1.0f : LOG2E;   // fold log2e into q

        #pragma unroll
        for (int it = 0; it < 16; ++it) {
            int idx = it * 256 + t;
            int d = idx >> 7, pr = idx & 127;
            float2 w = *(const float2*)&Wp[d * CC + 2 * pr];
            __half h0 = __float2half_rn(w.x), h1 = __float2half_rn(w.y);
            WH[d * 132 + pr] = pk2h(h0, h1);
            WL[d * 132 + pr] = pk2(w.x - __half2float(h0), w.y - __half2float(h1));
        }

        float cq[2][2][4];
        #pragma unroll
        for (int mm = 0; mm < 2; ++mm)
            #pragma unroll
            for (int n = 0; n < 2; ++n)
                #pragma unroll
                for (int k = 0; k < 4; ++k) cq[mm][n][k] = 0.f;

        for (int chunk = 0; chunk < 4; ++chunk) {
            __syncthreads();
            #pragma unroll
            for (int it = 0; it < 16; ++it) {
                int idx = it * 256 + t;
                int i = idx >> 7, px = idx & 127;
                size_t g = (size_t)(b * CC + chunk * 64 + 2 * i) * NN + px0 + px;
                float x0 = inp[g], x1 = inp[g + NN];
                __half h0 = __float2half_rn(x0), h1 = __float2half_rn(x1);
                INH[i * 136 + px] = pk2h(h0, h1);
                INL[i * 136 + px] = pk2(x0 - __half2float(h0), x1 - __half2float(h1));
            }
            __syncthreads();

            #pragma unroll
            for (int s = 0; s < 4; ++s) {
                uint32_t ah[2][4], al[2][4];
                const int ro  = (8 * s + lr) * 136;
                const int ro4 = (8 * s + lr + 4) * 136;
                #pragma unroll
                for (int mm = 0; mm < 2; ++mm) {
                    int pxm = wm * 32 + mm * 16 + lq;
                    ah[mm][0] = INH[ro + pxm];  ah[mm][1] = INH[ro + pxm + 8];
                    ah[mm][2] = INH[ro4 + pxm]; ah[mm][3] = INH[ro4 + pxm + 8];
                    al[mm][0] = INL[ro + pxm];  al[mm][1] = INL[ro + pxm + 8];
                    al[mm][2] = INL[ro4 + pxm]; al[mm][3] = INL[ro4 + pxm + 8];
                }
                #pragma unroll
                for (int n = 0; n < 2; ++n) {
                    int drow = ((wn * 2 + n) * 8 + lq) * 132 + chunk * 32;
                    uint32_t bh0 = WH[drow + 8 * s + lr];
                    uint32_t bh1 = WH[drow + 8 * s + lr + 4];
                    uint32_t bl0 = WL[drow + 8 * s + lr];
                    uint32_t bl1 = WL[drow + 8 * s + lr + 4];
                    #pragma unroll
                    for (int mm = 0; mm < 2; ++mm) {
                        mma16(cq[mm][n], ah[mm], bh0, bh1);
                        mma16(cq[mm][n], al[mm], bh0, bh1);
                        mma16(cq[mm][n], ah[mm], bl0, bl1);
                    }
                }
            }
        }

        #pragma unroll
        for (int mm = 0; mm < 2; ++mm) {
            #pragma unroll
            for (int n = 0; n < 2; ++n) {
                int pxr = px0 + wm * 32 + mm * 16 + lq;
                int d0  = (wn * 2 + n) * 8 + 2 * lr;
                float b0 = __ldg(&bp[d0]), b1 = __ldg(&bp[d0 + 1]);
                float q0 = (cq[mm][n][0] + b0) * scl, q1 = (cq[mm][n][1] + b1) * scl;
                float q2 = (cq[mm][n][2] + b0) * scl, q3 = (cq[mm][n][3] + b1) * scl;
                __half h0 = __float2half_rn(q0), h1 = __float2half_rn(q1);
                __half h2 = __float2half_rn(q2), h3 = __float2half_rn(q3);
                size_t i0w = (size_t)(b * NN + pxr) * 16 + (wn * 2 + n) * 4 + lr;
                oh[i0w]       = pk2h(h0, h1);
                ol[i0w]       = pk2(q0 - __half2float(h0), q1 - __half2float(h1));
                oh[i0w + 128] = pk2h(h2, h3);
                ol[i0w + 128] = pk2(q2 - __half2float(h2), q3 - __half2float(h3));
            }
        }
    }
}

// ---------------------------------------------------------------------------
// A: fp16 mma flash attention, 128-key tiles, V double-buffered,
// named-barrier max exchange, exp2 softmax. 512 thr, grid = 128.
// ---------------------------------------------------------------------------
#define SQH 0
#define SQL 10240
#define SKB 20480
#define SVB 40960
#define VBUF2 73728
#define SPS 188416
#define SLS 221184
#define SM_AT 223232

__device__ __forceinline__ void load_k2(uint32_t smb, const __half* kh,
                                        int j0, int buf, int t)
{
    int row128 = t >> 2, seg = t & 3;
    int half = row128 >> 6, row = row128 & 63;
    cp16(smb + SKB + (buf * 2 + half) * 5120 + row * 80 + seg * 16,
         kh + (size_t)(j0 + half * 64 + row) * DD + seg * 8);
}
__device__ __forceinline__ void load_v2(uint32_t smb, const __half* vh,
                                        int j0, int vbuf, int t)
{
    #pragma unroll
    for (int i = 0; i < 8; ++i) {
        int idx = i * 512 + t;
        int c = idx >> 4, rest = idx & 15;
        int half = rest >> 3, seg = rest & 7;
        cp16(smb + SVB + vbuf * VBUF2 + half * 36864 + c * 144 + seg * 16,
             vh + (size_t)c * NN + j0 + half * 64 + seg * 8);
    }
}

__global__ void __launch_bounds__(512, 1)
attn_mma_kernel(const float* __restrict__ sem, const float* __restrict__ gammaP,
                float* __restrict__ out)
{
    extern __shared__ char smc[];
    const uint32_t smb = s2u(smc);
    float* red = (float*)(smc + SLS);

    const int t    = threadIdx.x;
    const int lane = t & 31;
    const int wid  = t >> 5;
    const int wm   = wid & 3;
    const int wn   = wid >> 2;
    const int R0   = wm * 32;
    const int J0   = wn * 16;
    const int C0w  = wn * 64;
    const int lq   = lane >> 2;
    const int lr   = lane & 3;
    const int l8   = lane & 7;
    const int gp   = lane >> 3;
    const int pgb  = (gp & 2) >> 1;

    const int b  = blockIdx.x >> 5;
    const int i0 = (blockIdx.x & 31) << 7;

    const __half* khb = g_kh + (size_t)b * NN * DD;
    const __half* vhb = g_vh + (size_t)b * CC * NN;

    // preload Q (hi+lo), K(0), V(0)
    #pragma unroll
    for (int i = 0; i < 2; ++i) {
        int idx = i * 512 + t;
        int row = (idx >> 2) & 127, seg = idx & 3;
        const __half* src = (idx < 512 ? g_qh : g_ql) +
                            ((size_t)(b * NN + i0 + row)) * DD + seg * 8;
        cp16(smb + (idx < 512 ? SQH : SQL) + row * 80 + seg * 16, src);
    }
    load_k2(smb, khb, 0, 0, t);
    load_v2(smb, vhb, 0, 0, t);
    cp_commit();
    cp_wait0();
    __syncthreads();

    float oacc[2][8][4];
    #pragma unroll
    for (int m = 0; m < 2; ++m)
        #pragma unroll
        for (int n = 0; n < 8; ++n)
            #pragma unroll
            for (int k = 0; k < 4; ++k) oacc[m][n][k] = 0.f;
    float lsum[4] = {0.f, 0.f, 0.f, 0.f};
    float mrun[4] = {-1e30f, -1e30f, -1e30f, -1e30f};

    for (int kt = 0; kt < NT2; ++kt) {
        const int buf = kt & 1;
        if (kt + 1 < NT2) {
            load_k2(smb, khb, (kt + 1) * KT2, buf ^ 1, t);
            cp_commit();
        }

        // ---- S = Q K^T over 128 keys (2-term); S in log2 units ----
        float sacc[2][4][4];
        #pragma unroll
        for (int m = 0; m < 2; ++m)
            #pragma unroll
            for (int jn = 0; jn < 4; ++jn)
                #pragma unroll
                for (int k = 0; k < 4; ++k) sacc[m][jn][k] = 0.f;

        #pragma unroll
        for (int s = 0; s < 2; ++s) {
            uint32_t qh[2][4], ql[2][4];
            #pragma unroll
            for (int m = 0; m < 2; ++m) {
                int qrow = R0 + 16 * m + l8 + ((gp & 1) << 3);
                int qcol = 16 * s + ((gp & 2) << 2);
                uint32_t qa = smb + SQH + (qrow * 40 + qcol) * 2;
                LDSM4(qh[m], qa);
                LDSM4(ql[m], qa + (SQL - SQH));
            }
            int krow = J0 + l8 + ((gp & 2) << 2);
            int kcol = 16 * s + ((gp & 1) << 3);
            #pragma unroll
            for (int half = 0; half < 2; ++half) {
                uint32_t kbase = smb + SKB + (buf * 2 + half) * 5120;
                uint32_t kh[4];
                LDSM4(kh, kbase + (krow * 40 + kcol) * 2);
                #pragma unroll
                for (int n = 0; n < 2; ++n) {
                    #pragma unroll
                    for (int m = 0; m < 2; ++m) {
                        mma16(sacc[m][half * 2 + n], qh[m], kh[2 * n], kh[2 * n + 1]);
                        mma16(sacc[m][half * 2 + n], ql[m], kh[2 * n], kh[2 * n + 1]);
                    }
                }
            }
        }

        // ---- per-tile max partials ----
        float smax[4];
        #pragma unroll
        for (int m = 0; m < 2; ++m) {
            float a = -1e30f, c = -1e30f;
            #pragma unroll
            for (int jn = 0; jn < 4; ++jn) {
                a = fmaxf(a, fmaxf(sacc[m][jn][0], sacc[m][jn][1]));
                c = fmaxf(c, fmaxf(sacc[m][jn][2], sacc[m][jn][3]));
            }
            smax[2 * m] = a;
            smax[2 * m + 1] = c;
        }
        #pragma unroll
        for (int i = 0; i < 4; ++i) {
            smax[i] = fmaxf(smax[i], __shfl_xor_sync(0xFFFFFFFFu, smax[i], 1));
            smax[i] = fmaxf(smax[i], __shfl_xor_sync(0xFFFFFFFFu, smax[i], 2));
        }
        if (lr == 0) {
            #pragma unroll
            for (int i = 0; i < 4; ++i)
                red[wn * 128 + R0 + 8 * i + lq] = smax[i];
        }
        BARN(1 + wm);     // sync A: only the 4 warps sharing rows R0

        // ---- running max, f = exp2, rescale oacc ----
        float f[4];
        #pragma unroll
        for (int i = 0; i < 4; ++i) {
            int r = R0 + 8 * i + lq;
            float mt = fmaxf(fmaxf(red[r], red[128 + r]),
                             fmaxf(red[256 + r], red[384 + r]));
            float mn = fmaxf(mrun[i], mt);
            f[i] = ex2(mrun[i] - mn);
            mrun[i] = mn;
            lsum[i] *= f[i];
        }
        if (kt > 0 && (f[0] < 1.f || f[1] < 1.f || f[2] < 1.f || f[3] < 1.f)) {
            #pragma unroll
            for (int m = 0; m < 2; ++m)
                #pragma unroll
                for (int n = 0; n < 8; ++n) {
                    oacc[m][n][0] *= f[2 * m];
                    oacc[m][n][1] *= f[2 * m];
                    oacc[m][n][2] *= f[2 * m + 1];
                    oacc[m][n][3] *= f[2 * m + 1];
                }
        }

        // ---- P = exp2(s - m), l partials, store ----
        #pragma unroll
        for (int m = 0; m < 2; ++m) {
            int r = R0 + 16 * m + lq;
            #pragma unroll
            for (int jn = 0; jn < 4; ++jn) {
                int h = (jn >> 1) * 8 + wn * 2 + (jn & 1);
                float p0 = ex2(sacc[m][jn][0] - mrun[2 * m]);
                float p1 = ex2(sacc[m][jn][1] - mrun[2 * m]);
                float p2 = ex2(sacc[m][jn][2] - mrun[2 * m + 1]);
                float p3 = ex2(sacc[m][jn][3] - mrun[2 * m + 1]);
                lsum[2 * m]     += p0 + p1;
                lsum[2 * m + 1] += p2 + p3;
                uint32_t a0 = smb + SPS + r * 256 + ((h ^ lq) << 4) + lr * 4;
                asm volatile("st.shared.b32 [%0], %1;" :: "r"(a0), "r"(pk2(p0, p1)) : "memory");
                asm volatile("st.shared.b32 [%0], %1;" :: "r"(a0 + 2048), "r"(pk2(p2, p3)) : "memory");
            }
        }
        if (kt + 1 < NT2) cp_wait1(); else cp_wait0();
        __syncthreads();   // sync B (block): P visible, V(kt) resident

        // V(kt+1) prefetch (safe: all warps past PV(kt-1) on buf^1 at sync B)
        if (kt + 1 < NT2) {
            load_v2(smb, vhb, (kt + 1) * KT2, buf ^ 1, t);
            cp_commit();
        }

        // ---- PV over 128 keys from V[buf] ----
        const uint32_t vbb = smb + SVB + buf * VBUF2;
        #pragma unroll
        for (int kk = 0; kk < 8; ++kk) {
            uint32_t pa[2][4];
            #pragma unroll
            for (int m = 0; m < 2; ++m) {
                int prow = R0 + 16 * m + l8 + ((gp & 1) << 3);
                int pch  = 2 * kk + pgb;
                uint32_t paadr = smb + SPS + prow * 256 + ((pch ^ (prow & 7)) << 4);
                LDSM4(pa[m], paadr);
            }
            const int half = kk >> 2;
            const int vco  = 16 * (kk & 3) + ((gp & 1) << 3);
            const uint32_t vb = vbb + half * 36864;
            #pragma unroll
            for (int np = 0; np < 4; ++np) {
                int vrow = C0w + 16 * np + l8 + ((gp & 2) << 2);
                uint32_t va = vb + (vrow * 72 + vco) * 2;
                uint32_t vv[4];
                LDSM4(vv, va);
                mma16(oacc[0][2 * np],     pa[0], vv[0], vv[1]);
                mma16(oacc[0][2 * np + 1], pa[0], vv[2], vv[3]);
                mma16(oacc[1][2 * np],     pa[1], vv[0], vv[1]);
                mma16(oacc[1][2 * np + 1], pa[1], vv[2], vv[3]);
            }
        }
    }

    // ---- l reduction ----
    #pragma unroll
    for (int i = 0; i < 4; ++i) {
        lsum[i] += __shfl_xor_sync(0xFFFFFFFFu, lsum[i], 1);
        lsum[i] += __shfl_xor_sync(0xFFFFFFFFu, lsum[i], 2);
    }
    __syncthreads();
    if (lr == 0) {
        #pragma unroll
        for (int i = 0; i < 4; ++i)
            red[wn * 128 + R0 + 8 * i + lq] = lsum[i];
    }
    __syncthreads();

    float linv[4];
    #pragma unroll
    for (int i = 0; i < 4; ++i) {
        int r = R0 + 8 * i + lq;
        linv[i] = 1.f / (red[r] + red[128 + r] + red[256 + r] + red[384 + r]);
    }

    // ---- epilogue ----
    const float g = gammaP[0];
    #pragma unroll
    for (int m = 0; m < 2; ++m) {
        #pragma unroll
        for (int n = 0; n < 8; ++n) {
            int ch = C0w + 8 * n + 2 * lr;
            size_t ia = ((size_t)(b * CC + ch)) * NN + i0 + R0 + 16 * m + lq;
            out[ia]          = g * oacc[m][n][0] * linv[2 * m]     + sem[ia];
            out[ia + NN]     = g * oacc[m][n][1] * linv[2 * m]     + sem[ia + NN];
            out[ia + 8]      = g * oacc[m][n][2] * linv[2 * m + 1] + sem[ia + 8];
            out[ia + NN + 8] = g * oacc[m][n][3] * linv[2 * m + 1] + sem[ia + NN + 8];
        }
    }
}

// ---------------------------------------------------------------------------
extern "C" void kernel_launch(void* const* d_in, const int* in_sizes, int n_in,
                              void* d_out, int out_size)
{
    const float* sem = (const float*)d_in[0];
    const float* str = (const float*)d_in[1];
    const float* Wq  = (const float*)d_in[2];
    const float* bq  = (const float*)d_in[3];
    const float* Wk  = (const float*)d_in[4];
    const float* bk  = (const float*)d_in[5];
    const float* Wv  = (const float*)d_in[6];
    const float* bv  = (const float*)d_in[7];
    const float* gam = (const float*)d_in[8];
    float* out = (float*)d_out;

    const int smem_pf = PF_TOT * 4;
    const int smem_at = SM_AT;

    cudaFuncSetAttribute(proj_fused,
        cudaFuncAttributeMaxDynamicSharedMemorySize, smem_pf);
    cudaFuncSetAttribute(attn_mma_kernel,
        cudaFuncAttributeMaxDynamicSharedMemorySize, smem_at);

    proj_fused<<<512, 256, smem_pf>>>(sem, str, Wq, bq, Wk, bk, Wv, bv);
    attn_mma_kernel<<<BB * (NN / 128), 512, smem_at>>>(sem, gam, out);
}